// round 2
// baseline (speedup 1.0000x reference)
#include <cuda_runtime.h>
#include <cuda_bf16.h>
#include <math.h>

// Problem constants
#define D_MODEL 512
#define H_ 8
#define HD_ 64
#define ETA_ 4
#define R_ 8
#define D_FFC 2048
#define T_ 128
#define B_ 32
#define NTOK (T_*B_)            // 4096
#define TOTAL_PROJ 2656         // H*HD*5 + H*ETA*3
#define KQV_DIM 2560            // H*HD*5

// ---------------------------------------------------------------------------
// Scratch (static device arrays; no runtime allocation)
// ---------------------------------------------------------------------------
__device__ float g_xnorm  [NTOK * D_MODEL];     // ln1 out, reused as ffc_in
__device__ float g_allproj[NTOK * TOTAL_PROJ];
__device__ float g_attncore[NTOK * D_MODEL];    // pre-w_attn attention result
__device__ float g_attnrelu[NTOK * D_MODEL];    // relu(attn @ w_attn + b)
__device__ float g_Y3     [NTOK * 3 * D_MODEL];
__device__ float g_X2     [NTOK * 2 * D_MODEL];
__device__ float g_rx     [NTOK * D_MODEL];
__device__ float g_zb     [NTOK * D_MODEL];
__device__ float g_RX     [NTOK * D_MODEL];
__device__ float g_gate1  [NTOK * D_MODEL];
__device__ float g_hid    [NTOK * D_FFC];
__device__ float g_ffout  [NTOK * D_MODEL];

__device__ __forceinline__ float sigf(float x) { return 1.0f / (1.0f + expf(-x)); }

// ---------------------------------------------------------------------------
// LayerNorm: one block per row of 512
// ---------------------------------------------------------------------------
__global__ __launch_bounds__(256)
void ln_kernel(const float* __restrict__ x, const float* __restrict__ g,
               const float* __restrict__ b, float* __restrict__ y)
{
    __shared__ float rbuf[8];
    __shared__ float smean, srstd;
    const int row = blockIdx.x;
    const int tid = threadIdx.x;
    const int lane = tid & 31, warp = tid >> 5;
    const float* xr = x + (size_t)row * D_MODEL;

    float v0 = xr[tid], v1 = xr[tid + 256];

    // mean
    float s = v0 + v1;
    #pragma unroll
    for (int o = 16; o; o >>= 1) s += __shfl_down_sync(0xffffffffu, s, o);
    if (!lane) rbuf[warp] = s;
    __syncthreads();
    if (warp == 0) {
        float t = (lane < 8) ? rbuf[lane] : 0.0f;
        #pragma unroll
        for (int o = 4; o; o >>= 1) t += __shfl_down_sync(0xffffffffu, t, o);
        if (!lane) smean = t * (1.0f / D_MODEL);
    }
    __syncthreads();
    float m = smean;

    float d0 = v0 - m, d1 = v1 - m;
    float sv = d0 * d0 + d1 * d1;
    #pragma unroll
    for (int o = 16; o; o >>= 1) sv += __shfl_down_sync(0xffffffffu, sv, o);
    if (!lane) rbuf[warp] = sv;
    __syncthreads();
    if (warp == 0) {
        float t = (lane < 8) ? rbuf[lane] : 0.0f;
        #pragma unroll
        for (int o = 4; o; o >>= 1) t += __shfl_down_sync(0xffffffffu, t, o);
        if (!lane) srstd = rsqrtf(t * (1.0f / D_MODEL) + 1e-5f);
    }
    __syncthreads();
    float r = srstd;

    float* yr = y + (size_t)row * D_MODEL;
    yr[tid]       = d0 * r * g[tid]       + b[tid];
    yr[tid + 256] = d1 * r * g[tid + 256] + b[tid + 256];
}

// ---------------------------------------------------------------------------
// GEMM: C[M,N] = act(A[M,K] @ B[N,K]^T + bias), both row-major (NT form)
// 128x128 block, 16 k-tile, 256 threads, 8x8 per thread
// ---------------------------------------------------------------------------
template<int ACT>  // 0=none, 1=relu
__global__ __launch_bounds__(256)
void gemm_nt(const float* __restrict__ A, const float* __restrict__ B,
             const float* __restrict__ bias, float* __restrict__ C,
             int M, int N, int K)
{
    __shared__ float As[16][128];
    __shared__ float Bs[16][128];

    const int tid = threadIdx.x;
    const int bm = blockIdx.y * 128;
    const int bn = blockIdx.x * 128;
    const int ty = tid >> 4;   // 0..15
    const int tx = tid & 15;   // 0..15

    float acc[8][8];
    #pragma unroll
    for (int i = 0; i < 8; ++i)
        #pragma unroll
        for (int j = 0; j < 8; ++j) acc[i][j] = 0.0f;

    for (int k0 = 0; k0 < K; k0 += 16) {
        #pragma unroll
        for (int l = 0; l < 2; ++l) {
            int id = tid + l * 256;
            int row = id >> 2, kq = (id & 3) << 2;
            float4 v = *reinterpret_cast<const float4*>(
                &A[(size_t)(bm + row) * K + k0 + kq]);
            As[kq + 0][row] = v.x; As[kq + 1][row] = v.y;
            As[kq + 2][row] = v.z; As[kq + 3][row] = v.w;
        }
        #pragma unroll
        for (int l = 0; l < 2; ++l) {
            int id = tid + l * 256;
            int row = id >> 2, kq = (id & 3) << 2;
            float4 v = make_float4(0.f, 0.f, 0.f, 0.f);
            if (bn + row < N)
                v = *reinterpret_cast<const float4*>(
                    &B[(size_t)(bn + row) * K + k0 + kq]);
            Bs[kq + 0][row] = v.x; Bs[kq + 1][row] = v.y;
            Bs[kq + 2][row] = v.z; Bs[kq + 3][row] = v.w;
        }
        __syncthreads();

        #pragma unroll
        for (int k = 0; k < 16; ++k) {
            float ra[8], rb[8];
            #pragma unroll
            for (int i = 0; i < 8; ++i) ra[i] = As[k][ty * 8 + i];
            #pragma unroll
            for (int j = 0; j < 8; ++j) rb[j] = Bs[k][tx * 8 + j];
            #pragma unroll
            for (int i = 0; i < 8; ++i)
                #pragma unroll
                for (int j = 0; j < 8; ++j)
                    acc[i][j] = fmaf(ra[i], rb[j], acc[i][j]);
        }
        __syncthreads();
    }

    #pragma unroll
    for (int i = 0; i < 8; ++i) {
        int row = bm + ty * 8 + i;
        float* cr = C + (size_t)row * N;
        #pragma unroll
        for (int j = 0; j < 8; ++j) {
            int col = bn + tx * 8 + j;
            if (col < N) {
                float v = acc[i][j];
                if (bias) v += bias[col];
                if (ACT == 1) v = fmaxf(v, 0.0f);
                cr[col] = v;
            }
        }
    }
}

// ---------------------------------------------------------------------------
// Fused scan + attention-core kernel.
// One block per (b,h). State kept in registers across the T=128 scan.
//   K-state: (R=8, E=256)  -> thread e owns Kst[0..7]
//   S-state: (E=256)       -> thread e owns S
//   V-state: (R=8, D=64)   -> thread tid owns (r0,d2) and (r0+4,d2)
// ---------------------------------------------------------------------------
__global__ __launch_bounds__(256)
void scan_kernel(const float* __restrict__ allproj, const int* __restrict__ terms,
                 const float* __restrict__ tick, const float* __restrict__ tk,
                 const float* __restrict__ tv, const float* __restrict__ s_prev,
                 float* __restrict__ attn_core)
{
    const int bh = blockIdx.x;
    const int b = bh >> 3, h = bh & 7;
    const int tid = threadIdx.x;
    const int lane = tid & 31, warp = tid >> 5;

    __shared__ float sk[64], sq[64], sv[64], sb[64], sg[64];
    __shared__ float sp[12], socc[8];
    __shared__ float red[9 * 8];
    __shared__ float kdqn[9];
    __shared__ float kvpart[256];
    __shared__ float sterm;

    const int d  = tid >> 2, j = tid & 3;   // e = d*4 + j (K/S side)
    const int d2 = tid & 63, r0 = tid >> 6; // V side

    float Kst[8], S, V0, V1;
    #pragma unroll
    for (int r = 0; r < 8; ++r)
        Kst[r] = tk[(((size_t)b * R_ + r) * H_ + h) * 256 + tid];
    S  = s_prev[((size_t)b * H_ + h) * 256 + tid];
    V0 = tv[(((size_t)b * R_ + r0    ) * H_ + h) * 64 + d2];
    V1 = tv[(((size_t)b * R_ + r0 + 4) * H_ + h) * 64 + d2];
    const float tickb = tick[b];

    for (int t = 0; t < T_; ++t) {
        const size_t rowbase = ((size_t)t * B_ + b) * TOTAL_PROJ;
        const float* ap = allproj + rowbase + h * 320;
        if (tid < 64) {
            sk[tid] = ap[tid];
            sq[tid] = ap[64 + tid];
            sv[tid] = ap[128 + tid];
            sb[tid] = ap[192 + tid];
            sg[tid] = ap[256 + tid];
        } else if (tid < 76) {
            sp[tid - 64] = allproj[rowbase + KQV_DIM + h * 12 + (tid - 64)];
        } else if (tid >= 96 && tid < 104) {
            int u = tid - 96;
            float om = -3.14159265358979323846f
                     + (float)u * (6.28318530717958647692f / 7.0f);
            socc[u] = cosf((tickb + (float)(t + 1)) * om);
        } else if (tid == 255) {
            sterm = 1.0f - (float)terms[t * B_ + b];
        }
        __syncthreads();

        const float term = sterm;

        // --- K / S side (thread = e) ---
        float ke = fmaxf(sk[d], 0.0f) * fmaxf(sp[j], 0.0f);
        float qe = fmaxf(sq[d], 0.0f) * fmaxf(sp[4 + j], 0.0f);
        float ge = sigf(sg[d]) * sigf(sp[8 + j]);
        float kg = ke * ge;
        float dg = (1.0f - ge) * term;
        S = fmaf(dg, S, kg);
        float loc[9];
        #pragma unroll
        for (int r = 0; r < 8; ++r) {
            Kst[r] = fmaf(dg, Kst[r], kg * socc[r]);
            loc[r] = Kst[r] * qe;
        }
        loc[8] = S * qe;

        // --- V side (thread = (r0,d2) and (r0+4,d2)) ---
        float bs = sigf(sb[d2]);
        float vg = sv[d2] * bs;
        float db = (1.0f - bs) * term;
        V0 = fmaf(db, V0, vg * socc[r0]);
        V1 = fmaf(db, V1, vg * socc[r0 + 4]);

        // --- 9 block reductions (kdq[0..7], norm) ---
        #pragma unroll
        for (int v = 0; v < 9; ++v) {
            float x = loc[v];
            x += __shfl_down_sync(0xffffffffu, x, 16);
            x += __shfl_down_sync(0xffffffffu, x, 8);
            x += __shfl_down_sync(0xffffffffu, x, 4);
            x += __shfl_down_sync(0xffffffffu, x, 2);
            x += __shfl_down_sync(0xffffffffu, x, 1);
            if (lane == 0) red[v * 8 + warp] = x;
        }
        __syncthreads();
        if (tid < 9) {
            float s = 0.0f;
            #pragma unroll
            for (int w = 0; w < 8; ++w) s += red[tid * 8 + w];
            kdqn[tid] = (tid == 8) ? (s + 1e-6f) : s;
        }
        __syncthreads();

        // --- kv over r ---
        kvpart[tid] = V0 * kdqn[r0] + V1 * kdqn[r0 + 4];
        __syncthreads();
        if (tid < 64) {
            float kv = kvpart[tid] + kvpart[64 + tid]
                     + kvpart[128 + tid] + kvpart[192 + tid];
            attn_core[((size_t)t * B_ + b) * D_MODEL + h * 64 + tid] =
                kv / (16.0f * kdqn[8]);
        }
        __syncthreads();
    }
}

// ---------------------------------------------------------------------------
// GRU stage 1: given Y3 = y@w^T (stride 1536) and X2 = x@u[0:2]^T (stride 1024):
//   r = sig(Y0+X0); z = sig(Y1+X1-2); rx = r*x
// ---------------------------------------------------------------------------
__global__ __launch_bounds__(256)
void gru_pre(const float* __restrict__ x, const float* __restrict__ Y3,
             const float* __restrict__ X2, float* __restrict__ rx,
             float* __restrict__ z, int n)
{
    int idx = blockIdx.x * blockDim.x + threadIdx.x;
    if (idx >= n) return;
    int row = idx >> 9, c = idx & 511;
    size_t yb = (size_t)row * (3 * D_MODEL) + c;
    size_t xb = (size_t)row * (2 * D_MODEL) + c;
    float r = sigf(Y3[yb] + X2[xb]);
    z[idx]  = sigf(Y3[yb + 512] + X2[xb + 512] - 2.0f);
    rx[idx] = r * x[idx];
}

// ---------------------------------------------------------------------------
// GRU stage 2: h = tanh(Y2 + RX); out = (1-z)*x + z*h
// ---------------------------------------------------------------------------
__global__ __launch_bounds__(256)
void gru_post(const float* __restrict__ x, const float* __restrict__ Y3,
              const float* __restrict__ RX, const float* __restrict__ z,
              float* __restrict__ out, int n)
{
    int idx = blockIdx.x * blockDim.x + threadIdx.x;
    if (idx >= n) return;
    int row = idx >> 9, c = idx & 511;
    float hh = tanhf(Y3[(size_t)row * (3 * D_MODEL) + 1024 + c] + RX[idx]);
    float zz = z[idx];
    out[idx] = (1.0f - zz) * x[idx] + zz * hh;
}

// ---------------------------------------------------------------------------
// Launch
// ---------------------------------------------------------------------------
static float* symptr(const void* sym) {
    void* p = nullptr;
    cudaGetSymbolAddress(&p, sym);
    return (float*)p;
}

extern "C" void kernel_launch(void* const* d_in, const int* in_sizes, int n_in,
                              void* d_out, int out_size)
{
    const float* inputs   = (const float*)d_in[0];
    const int*   terms    = (const int*)  d_in[1];
    const float* tilde_k  = (const float*)d_in[2];
    const float* tilde_v  = (const float*)d_in[3];
    const float* s_prev   = (const float*)d_in[4];
    const float* tick     = (const float*)d_in[5];
    const float* w_proj   = (const float*)d_in[6];
    const float* b_proj   = (const float*)d_in[7];
    const float* w_attn   = (const float*)d_in[8];
    const float* b_attn   = (const float*)d_in[9];
    const float* ln1_g    = (const float*)d_in[10];
    const float* ln1_b    = (const float*)d_in[11];
    const float* ln2_g    = (const float*)d_in[12];
    const float* ln2_b    = (const float*)d_in[13];
    const float* gru1_w   = (const float*)d_in[14];
    const float* gru1_u   = (const float*)d_in[15];
    const float* gru2_w   = (const float*)d_in[16];
    const float* gru2_u   = (const float*)d_in[17];
    const float* ffc_w1   = (const float*)d_in[18];
    const float* ffc_b1   = (const float*)d_in[19];
    const float* ffc_w2   = (const float*)d_in[20];
    const float* ffc_b2   = (const float*)d_in[21];
    float* out = (float*)d_out;

    float* xnorm    = symptr(g_xnorm);
    float* allproj  = symptr(g_allproj);
    float* attncore = symptr(g_attncore);
    float* attnrelu = symptr(g_attnrelu);
    float* Y3       = symptr(g_Y3);
    float* X2       = symptr(g_X2);
    float* rx       = symptr(g_rx);
    float* zb       = symptr(g_zb);
    float* RX       = symptr(g_RX);
    float* gate1    = symptr(g_gate1);
    float* hid      = symptr(g_hid);
    float* ffout    = symptr(g_ffout);

    const int n = NTOK * D_MODEL;          // 2,097,152
    dim3 thr(256);
    const int eg = (n + 255) / 256;

    // 1) ln1(inputs) -> xnorm
    ln_kernel<<<NTOK, thr>>>(inputs, ln1_g, ln1_b, xnorm);

    // 2) all_proj = xnorm @ w_proj^T + b_proj   (4096 x 2656 x 512)
    gemm_nt<0><<<dim3((TOTAL_PROJ + 127) / 128, NTOK / 128), thr>>>(
        xnorm, w_proj, b_proj, allproj, NTOK, TOTAL_PROJ, D_MODEL);

    // 3) fused scan + attention core -> attncore (4096 x 512)
    scan_kernel<<<B_ * H_, thr>>>(allproj, terms, tick, tilde_k, tilde_v,
                                  s_prev, attncore);

    // 4) attnrelu = relu(attncore @ w_attn^T + b_attn)
    gemm_nt<1><<<dim3(4, NTOK / 128), thr>>>(
        attncore, w_attn, b_attn, attnrelu, NTOK, D_MODEL, D_MODEL);

    // 5) GRU1: x = inputs, y = attnrelu
    gemm_nt<0><<<dim3(12, NTOK / 128), thr>>>(
        attnrelu, gru1_w, nullptr, Y3, NTOK, 3 * D_MODEL, D_MODEL);
    gemm_nt<0><<<dim3(8, NTOK / 128), thr>>>(
        inputs, gru1_u, nullptr, X2, NTOK, 2 * D_MODEL, D_MODEL);
    gru_pre<<<eg, thr>>>(inputs, Y3, X2, rx, zb, n);
    gemm_nt<0><<<dim3(4, NTOK / 128), thr>>>(
        rx, gru1_u + (size_t)2 * D_MODEL * D_MODEL, nullptr, RX,
        NTOK, D_MODEL, D_MODEL);
    gru_post<<<eg, thr>>>(inputs, Y3, RX, zb, gate1, n);

    // 6) ln2(gate1) -> xnorm (reuse)
    ln_kernel<<<NTOK, thr>>>(gate1, ln2_g, ln2_b, xnorm);

    // 7) FFC
    gemm_nt<1><<<dim3(16, NTOK / 128), thr>>>(
        xnorm, ffc_w1, ffc_b1, hid, NTOK, D_FFC, D_MODEL);
    gemm_nt<1><<<dim3(4, NTOK / 128), thr>>>(
        hid, ffc_w2, ffc_b2, ffout, NTOK, D_MODEL, D_FFC);

    // 8) GRU2: x = gate1, y = ffout
    gemm_nt<0><<<dim3(12, NTOK / 128), thr>>>(
        ffout, gru2_w, nullptr, Y3, NTOK, 3 * D_MODEL, D_MODEL);
    gemm_nt<0><<<dim3(8, NTOK / 128), thr>>>(
        gate1, gru2_u, nullptr, X2, NTOK, 2 * D_MODEL, D_MODEL);
    gru_pre<<<eg, thr>>>(gate1, Y3, X2, rx, zb, n);
    gemm_nt<0><<<dim3(4, NTOK / 128), thr>>>(
        rx, gru2_u + (size_t)2 * D_MODEL * D_MODEL, nullptr, RX,
        NTOK, D_MODEL, D_MODEL);
    gru_post<<<eg, thr>>>(gate1, Y3, RX, zb, out, n);
}

// round 5
// speedup vs baseline: 1.7479x; 1.7479x over previous
#include <cuda_runtime.h>
#include <cuda_bf16.h>
#include <math.h>
#include <stdint.h>

// Problem constants
#define D_MODEL 512
#define H_ 8
#define HD_ 64
#define ETA_ 4
#define R_ 8
#define D_FFC 2048
#define T_ 128
#define B_ 32
#define NTOK (T_*B_)            // 4096
#define TOTAL_PROJ 2656
#define KQV_DIM 2560

typedef __nv_bfloat16 bf16;

#if defined(__CUDA_ARCH_FEAT_SM103_ALL) || defined(__CUDA_ARCH_FEAT_SM100_ALL)
#define HAS_TCGEN05 1
#else
#define HAS_TCGEN05 0
#endif

// ---------------------------------------------------------------------------
// Scratch (static device arrays; no runtime allocation)
// ---------------------------------------------------------------------------
__device__ float g_allproj[NTOK * TOTAL_PROJ];
__device__ float g_Y3   [NTOK * 3 * D_MODEL];
__device__ float g_X2   [NTOK * 2 * D_MODEL];
__device__ float g_zb   [NTOK * D_MODEL];
__device__ float g_RX   [NTOK * D_MODEL];
__device__ float g_gate1[NTOK * D_MODEL];

// bf16 hi/lo activation pairs
__device__ bf16 g_in_h   [NTOK * D_MODEL], g_in_l   [NTOK * D_MODEL];
__device__ bf16 g_xn_h   [NTOK * D_MODEL], g_xn_l   [NTOK * D_MODEL];
__device__ bf16 g_core_h [NTOK * D_MODEL], g_core_l [NTOK * D_MODEL];
__device__ bf16 g_arelu_h[NTOK * D_MODEL], g_arelu_l[NTOK * D_MODEL];
__device__ bf16 g_rx_h   [NTOK * D_MODEL], g_rx_l   [NTOK * D_MODEL];
__device__ bf16 g_g1_h   [NTOK * D_MODEL], g_g1_l   [NTOK * D_MODEL];
__device__ bf16 g_ff_h   [NTOK * D_MODEL], g_ff_l   [NTOK * D_MODEL];
__device__ bf16 g_hid_h  [NTOK * D_FFC],   g_hid_l  [NTOK * D_FFC];

// bf16 hi/lo weight pairs
#define WPROJ_N (TOTAL_PROJ * D_MODEL)
#define WATTN_N (D_MODEL * D_MODEL)
#define WGRU_N  (3 * D_MODEL * D_MODEL)
#define WFFC1_N (D_FFC * D_MODEL)
#define WFFC2_N (D_MODEL * D_FFC)
__device__ bf16 g_wproj_h[WPROJ_N], g_wproj_l[WPROJ_N];
__device__ bf16 g_wattn_h[WATTN_N], g_wattn_l[WATTN_N];
__device__ bf16 g_g1w_h[WGRU_N], g_g1w_l[WGRU_N];
__device__ bf16 g_g1u_h[WGRU_N], g_g1u_l[WGRU_N];
__device__ bf16 g_g2w_h[WGRU_N], g_g2w_l[WGRU_N];
__device__ bf16 g_g2u_h[WGRU_N], g_g2u_l[WGRU_N];
__device__ bf16 g_fw1_h[WFFC1_N], g_fw1_l[WFFC1_N];
__device__ bf16 g_fw2_h[WFFC2_N], g_fw2_l[WFFC2_N];

__device__ __forceinline__ float sigf(float x) { return 1.0f / (1.0f + expf(-x)); }

__device__ __forceinline__ void split1(float v, bf16* h, bf16* l) {
    bf16 hv = __float2bfloat16(v);
    *h = hv;
    *l = __float2bfloat16(v - __bfloat162float(hv));
}

__device__ __forceinline__ uint32_t smem_u32(const void* p) {
    uint32_t a;
    asm("{ .reg .u64 t; cvta.to.shared.u64 t, %1; cvt.u32.u64 %0, t; }"
        : "=r"(a) : "l"(p));
    return a;
}

#if HAS_TCGEN05
// ---------------------------------------------------------------------------
// tcgen05 PTX helpers (compiled ONLY on the sm_103a/sm_100a pass)
// ---------------------------------------------------------------------------
__device__ __forceinline__ uint32_t elect1() {
    uint32_t r;
    asm volatile("{\n\t.reg .pred p;\n\telect.sync _|p, 0xFFFFFFFF;\n\t"
                 "selp.b32 %0,1,0,p;\n\t}" : "=r"(r));
    return r;
}
__device__ __forceinline__ void tc_alloc(uint32_t saddr, uint32_t ncols) {
    asm volatile("tcgen05.alloc.cta_group::1.sync.aligned.shared::cta.b32 [%0], %1;"
                 :: "r"(saddr), "r"(ncols) : "memory");
}
__device__ __forceinline__ void tc_relinq() {
    asm volatile("tcgen05.relinquish_alloc_permit.cta_group::1.sync.aligned;");
}
__device__ __forceinline__ void tc_dealloc(uint32_t tmem, uint32_t ncols) {
    asm volatile("tcgen05.dealloc.cta_group::1.sync.aligned.b32 %0, %1;"
                 :: "r"(tmem), "r"(ncols));
}
__device__ __forceinline__ void mbar_init(uint32_t mb, uint32_t cnt) {
    asm volatile("mbarrier.init.shared.b64 [%0], %1;" :: "r"(mb), "r"(cnt) : "memory");
}
__device__ __forceinline__ void mbar_wait(uint32_t mb, uint32_t parity) {
    asm volatile("{\n\t.reg .pred P;\n\t"
                 "WL_%=:\n\t"
                 "mbarrier.try_wait.parity.acquire.cta.shared::cta.b64 P, [%0], %1, 0x989680;\n\t"
                 "@!P bra WL_%=;\n\t}"
                 :: "r"(mb), "r"(parity) : "memory");
}
__device__ __forceinline__ void tc_commit(uint32_t mb) {
    asm volatile("tcgen05.commit.cta_group::1.mbarrier::arrive::one.shared::cluster.b64 [%0];"
                 :: "r"(mb) : "memory");
}
__device__ __forceinline__ void fence_async_smem() {
    asm volatile("fence.proxy.async.shared::cta;" ::: "memory");
}
__device__ __forceinline__ void tc_fence_after() {
    asm volatile("tcgen05.fence::after_thread_sync;" ::: "memory");
}
__device__ __forceinline__ void tc_wait_ld() {
    asm volatile("tcgen05.wait::ld.sync.aligned;" ::: "memory");
}
__device__ __forceinline__ void mma_ss(uint32_t d, uint64_t a, uint64_t b,
                                       uint32_t idesc, bool en) {
    uint32_t e = en ? 1u : 0u;
    asm volatile("{\n\t.reg .pred p;\n\tsetp.ne.u32 p, %4, 0;\n\t"
                 "tcgen05.mma.cta_group::1.kind::f16 [%0], %1, %2, %3, "
                 "{%5, %5, %5, %5}, p;\n\t}"
                 :: "r"(d), "l"(a), "l"(b), "r"(idesc), "r"(e), "r"(0u)
                 : "memory");
}
__device__ __forceinline__ void ldtm32(uint32_t* r, uint32_t tmem) {
    asm volatile(
        "tcgen05.ld.sync.aligned.32x32b.x32.b32 "
        "{%0, %1, %2, %3, %4, %5, %6, %7, %8, %9, %10, %11, %12, %13, %14, %15, "
        "%16, %17, %18, %19, %20, %21, %22, %23, %24, %25, %26, %27, %28, %29, %30, %31}, [%32];"
        : "=r"(r[0]), "=r"(r[1]), "=r"(r[2]), "=r"(r[3]),
          "=r"(r[4]), "=r"(r[5]), "=r"(r[6]), "=r"(r[7]),
          "=r"(r[8]), "=r"(r[9]), "=r"(r[10]), "=r"(r[11]),
          "=r"(r[12]), "=r"(r[13]), "=r"(r[14]), "=r"(r[15]),
          "=r"(r[16]), "=r"(r[17]), "=r"(r[18]), "=r"(r[19]),
          "=r"(r[20]), "=r"(r[21]), "=r"(r[22]), "=r"(r[23]),
          "=r"(r[24]), "=r"(r[25]), "=r"(r[26]), "=r"(r[27]),
          "=r"(r[28]), "=r"(r[29]), "=r"(r[30]), "=r"(r[31])
        : "r"(tmem));
}
__device__ __forceinline__ uint64_t mk_desc(uint32_t saddr) {
    const uint64_t base = (uint64_t(2) << 61) | (uint64_t(1) << 46)
                        | (uint64_t(64) << 32) | (uint64_t(1) << 16);
    return base | ((uint64_t)(saddr >> 4) & 0x3FFF);
}
#define IDESC_128 ((1u << 4) | (1u << 7) | (1u << 10) | (16u << 17) | (8u << 24))
#endif // HAS_TCGEN05

// Fallback warp MMA (legal on any sm_80+ target, incl. plain sm_103)
__device__ __forceinline__ void mma16816(float* d, uint32_t a0, uint32_t a1,
                                         uint32_t a2, uint32_t a3,
                                         uint32_t b0, uint32_t b1) {
    asm volatile(
        "mma.sync.aligned.m16n8k16.row.col.f32.bf16.bf16.f32 "
        "{%0,%1,%2,%3}, {%4,%5,%6,%7}, {%8,%9}, {%0,%1,%2,%3};"
        : "+f"(d[0]), "+f"(d[1]), "+f"(d[2]), "+f"(d[3])
        : "r"(a0), "r"(a1), "r"(a2), "r"(a3), "r"(b0), "r"(b1));
}

// ---------------------------------------------------------------------------
// bf16-split GEMM: C[M,N] = act(A @ B^T + bias). Tile 128x128, K-chunk 64.
// SW128-swizzled smem tiles Ah/Al/Bh/Bl (128 rows x 128B each).
// sm_103a pass: tcgen05 SS MMA. Other passes: mma.sync m16n8k16 fallback.
// ---------------------------------------------------------------------------
#define SMEM_GEMM (1024 + 4 * 16384 + 1024)

template<int ACT, int OUTMODE>
__global__ __launch_bounds__(256)
void gemm_tc(const bf16* __restrict__ Ah, const bf16* __restrict__ Al,
             const bf16* __restrict__ Bh, const bf16* __restrict__ Bl,
             const float* __restrict__ bias,
             float* __restrict__ Cf, bf16* __restrict__ Ch, bf16* __restrict__ Cl,
             int M, int N, int K)
{
    extern __shared__ char dsm[];
    const uint32_t sraw = smem_u32(dsm);
    const uint32_t tile0 = (sraw + 1024u) & ~1023u;
    const uint32_t off0 = tile0 - sraw;

    const int tid = threadIdx.x;
    const int wid = tid >> 5, lid = tid & 31;
    const int bm = blockIdx.y * 128;
    const int bn = blockIdx.x * 128;
    char* smc = dsm;

#if HAS_TCGEN05
    const uint32_t tA_h = tile0;
    const uint32_t tA_l = tile0 + 16384;
    const uint32_t tB_h = tile0 + 2 * 16384;
    const uint32_t tB_l = tile0 + 3 * 16384;
    const uint32_t mbar = sraw + 8;

    if (wid == 0) { tc_alloc(sraw, 128); tc_relinq(); }
    if (tid == 0) mbar_init(mbar, 1);
    __syncthreads();
    uint32_t tmem;
    asm volatile("ld.shared.b32 %0, [%1];" : "=r"(tmem) : "r"(sraw));

    uint32_t phase = 0;
    for (int k0 = 0; k0 < K; k0 += 64) {
        #pragma unroll
        for (int p = 0; p < 4; ++p) {
            int id = tid + p * 256;
            int row = id >> 3, grp = id & 7;
            uint32_t boff = (uint32_t)(row * 128 + grp * 16);
            uint32_t sw = boff ^ ((boff >> 3) & 0x70);
            size_t aoff = (size_t)(bm + row) * K + k0 + grp * 8;
            *(float4*)(smc + off0 + sw)             = *(const float4*)(Ah + aoff);
            *(float4*)(smc + off0 + 16384 + sw)     = *(const float4*)(Al + aoff);
            float4 vh = make_float4(0.f, 0.f, 0.f, 0.f), vl = vh;
            if (bn + row < N) {
                size_t boff2 = (size_t)(bn + row) * K + k0 + grp * 8;
                vh = *(const float4*)(Bh + boff2);
                vl = *(const float4*)(Bl + boff2);
            }
            *(float4*)(smc + off0 + 2 * 16384 + sw) = vh;
            *(float4*)(smc + off0 + 3 * 16384 + sw) = vl;
        }
        fence_async_smem();
        __syncthreads();

        if (wid == 0) {
            if (elect1()) {
                uint64_t dah = mk_desc(tA_h), dal = mk_desc(tA_l);
                uint64_t dbh = mk_desc(tB_h), dbl = mk_desc(tB_l);
                #pragma unroll
                for (int ks = 0; ks < 4; ++ks) {
                    uint64_t o = (uint64_t)(ks * 2);
                    bool en0 = (k0 > 0) || (ks > 0);
                    mma_ss(tmem, dah + o, dbh + o, IDESC_128, en0);
                    mma_ss(tmem, dah + o, dbl + o, IDESC_128, true);
                    mma_ss(tmem, dal + o, dbh + o, IDESC_128, true);
                }
                tc_commit(mbar);
            }
        }
        mbar_wait(mbar, phase);
        phase ^= 1;
        __syncthreads();
    }

    tc_fence_after();

    if (wid < 4) {
        const int m = bm + wid * 32 + lid;
        #pragma unroll
        for (int nb = 0; nb < 4; ++nb) {
            uint32_t dr[32];
            ldtm32(dr, tmem + nb * 32);
            tc_wait_ld();
            #pragma unroll
            for (int c = 0; c < 32; ++c) {
                int col = bn + nb * 32 + c;
                if (col < N) {
                    float v = __uint_as_float(dr[c]);
                    if (bias) v += bias[col];
                    if (ACT) v = fmaxf(v, 0.0f);
                    size_t idx = (size_t)m * N + col;
                    if (OUTMODE == 0) {
                        Cf[idx] = v;
                    } else {
                        bf16 h = __float2bfloat16(v);
                        Ch[idx] = h;
                        Cl[idx] = __float2bfloat16(v - __bfloat162float(h));
                    }
                }
            }
        }
    }
    __syncthreads();
    if (wid == 0) tc_dealloc(tmem, 128);

#else  // ------------------- mma.sync fallback path -------------------------
    const int wm0 = (wid >> 2) * 64;   // warp grid 2(M) x 4(N)
    const int wn0 = (wid & 3) * 32;
    const int g = lid >> 2, tg = lid & 3;

    float acc[4][4][4];
    #pragma unroll
    for (int a = 0; a < 4; ++a)
        #pragma unroll
        for (int b = 0; b < 4; ++b)
            #pragma unroll
            for (int c = 0; c < 4; ++c) acc[a][b][c] = 0.0f;

    const uint32_t oA_h = off0, oA_l = off0 + 16384;
    const uint32_t oB_h = off0 + 32768, oB_l = off0 + 49152;

    for (int k0 = 0; k0 < K; k0 += 64) {
        #pragma unroll
        for (int p = 0; p < 4; ++p) {
            int id = tid + p * 256;
            int row = id >> 3, grp = id & 7;
            uint32_t boff = (uint32_t)(row * 128 + grp * 16);
            uint32_t sw = boff ^ ((boff >> 3) & 0x70);
            size_t aoff = (size_t)(bm + row) * K + k0 + grp * 8;
            *(float4*)(smc + oA_h + sw) = *(const float4*)(Ah + aoff);
            *(float4*)(smc + oA_l + sw) = *(const float4*)(Al + aoff);
            float4 vh = make_float4(0.f, 0.f, 0.f, 0.f), vl = vh;
            if (bn + row < N) {
                size_t boff2 = (size_t)(bn + row) * K + k0 + grp * 8;
                vh = *(const float4*)(Bh + boff2);
                vl = *(const float4*)(Bl + boff2);
            }
            *(float4*)(smc + oB_h + sw) = vh;
            *(float4*)(smc + oB_l + sw) = vl;
        }
        __syncthreads();

        #pragma unroll
        for (int ks = 0; ks < 4; ++ks) {
            const uint32_t kb = (uint32_t)(ks * 32 + tg * 4);
            // B fragments (hi & lo) for 4 n-tiles
            uint32_t bh0[4], bh1[4], bl0[4], bl1[4];
            #pragma unroll
            for (int nt = 0; nt < 4; ++nt) {
                uint32_t row = (uint32_t)(wn0 + nt * 8 + g);
                uint32_t o1 = row * 128 + kb;
                uint32_t o2 = o1 + 16;
                uint32_t s1 = o1 ^ ((o1 >> 3) & 0x70);
                uint32_t s2 = o2 ^ ((o2 >> 3) & 0x70);
                bh0[nt] = *(const uint32_t*)(smc + oB_h + s1);
                bh1[nt] = *(const uint32_t*)(smc + oB_h + s2);
                bl0[nt] = *(const uint32_t*)(smc + oB_l + s1);
                bl1[nt] = *(const uint32_t*)(smc + oB_l + s2);
            }
            #pragma unroll
            for (int mt = 0; mt < 4; ++mt) {
                uint32_t r0 = (uint32_t)(wm0 + mt * 16 + g);
                uint32_t o_r0c0 = r0 * 128 + kb;
                uint32_t o_r8c0 = o_r0c0 + 8 * 128;
                uint32_t o_r0c8 = o_r0c0 + 16;
                uint32_t o_r8c8 = o_r8c0 + 16;
                uint32_t s00 = o_r0c0 ^ ((o_r0c0 >> 3) & 0x70);
                uint32_t s80 = o_r8c0 ^ ((o_r8c0 >> 3) & 0x70);
                uint32_t s08 = o_r0c8 ^ ((o_r0c8 >> 3) & 0x70);
                uint32_t s88 = o_r8c8 ^ ((o_r8c8 >> 3) & 0x70);
                uint32_t ah0 = *(const uint32_t*)(smc + oA_h + s00);
                uint32_t ah1 = *(const uint32_t*)(smc + oA_h + s80);
                uint32_t ah2 = *(const uint32_t*)(smc + oA_h + s08);
                uint32_t ah3 = *(const uint32_t*)(smc + oA_h + s88);
                uint32_t al0 = *(const uint32_t*)(smc + oA_l + s00);
                uint32_t al1 = *(const uint32_t*)(smc + oA_l + s80);
                uint32_t al2 = *(const uint32_t*)(smc + oA_l + s08);
                uint32_t al3 = *(const uint32_t*)(smc + oA_l + s88);
                #pragma unroll
                for (int nt = 0; nt < 4; ++nt) {
                    mma16816(acc[mt][nt], ah0, ah1, ah2, ah3, bh0[nt], bh1[nt]);
                    mma16816(acc[mt][nt], ah0, ah1, ah2, ah3, bl0[nt], bl1[nt]);
                    mma16816(acc[mt][nt], al0, al1, al2, al3, bh0[nt], bh1[nt]);
                }
            }
        }
        __syncthreads();
    }

    // Epilogue
    #pragma unroll
    for (int mt = 0; mt < 4; ++mt) {
        #pragma unroll
        for (int nt = 0; nt < 4; ++nt) {
            int r0 = bm + wm0 + mt * 16 + g;
            int c0 = bn + wn0 + nt * 8 + tg * 2;
            #pragma unroll
            for (int half = 0; half < 2; ++half) {
                int row = r0 + half * 8;
                #pragma unroll
                for (int cc = 0; cc < 2; ++cc) {
                    int col = c0 + cc;
                    if (col < N) {
                        float v = acc[mt][nt][half * 2 + cc];
                        if (bias) v += bias[col];
                        if (ACT) v = fmaxf(v, 0.0f);
                        size_t idx = (size_t)row * N + col;
                        if (OUTMODE == 0) {
                            Cf[idx] = v;
                        } else {
                            bf16 h = __float2bfloat16(v);
                            Ch[idx] = h;
                            Cl[idx] = __float2bfloat16(v - __bfloat162float(h));
                        }
                    }
                }
            }
        }
    }
#endif
}

// ---------------------------------------------------------------------------
// Split fp32 -> bf16 hi/lo
// ---------------------------------------------------------------------------
__global__ __launch_bounds__(256)
void split_kernel(const float* __restrict__ x, bf16* __restrict__ h,
                  bf16* __restrict__ l, int n)
{
    int i = blockIdx.x * 256 + threadIdx.x;
    if (i < n) split1(x[i], h + i, l + i);
}

// ---------------------------------------------------------------------------
// LayerNorm: one block per row of 512, emits bf16 hi/lo
// ---------------------------------------------------------------------------
__global__ __launch_bounds__(256)
void ln_kernel(const float* __restrict__ x, const float* __restrict__ g,
               const float* __restrict__ b, bf16* __restrict__ yh,
               bf16* __restrict__ yl)
{
    __shared__ float rbuf[8];
    __shared__ float smean, srstd;
    const int row = blockIdx.x;
    const int tid = threadIdx.x;
    const int lane = tid & 31, warp = tid >> 5;
    const float* xr = x + (size_t)row * D_MODEL;

    float v0 = xr[tid], v1 = xr[tid + 256];

    float s = v0 + v1;
    #pragma unroll
    for (int o = 16; o; o >>= 1) s += __shfl_down_sync(0xffffffffu, s, o);
    if (!lane) rbuf[warp] = s;
    __syncthreads();
    if (warp == 0) {
        float t = (lane < 8) ? rbuf[lane] : 0.0f;
        #pragma unroll
        for (int o = 4; o; o >>= 1) t += __shfl_down_sync(0xffffffffu, t, o);
        if (!lane) smean = t * (1.0f / D_MODEL);
    }
    __syncthreads();
    float m = smean;

    float d0 = v0 - m, d1 = v1 - m;
    float sv = d0 * d0 + d1 * d1;
    #pragma unroll
    for (int o = 16; o; o >>= 1) sv += __shfl_down_sync(0xffffffffu, sv, o);
    if (!lane) rbuf[warp] = sv;
    __syncthreads();
    if (warp == 0) {
        float t = (lane < 8) ? rbuf[lane] : 0.0f;
        #pragma unroll
        for (int o = 4; o; o >>= 1) t += __shfl_down_sync(0xffffffffu, t, o);
        if (!lane) srstd = rsqrtf(t * (1.0f / D_MODEL) + 1e-5f);
    }
    __syncthreads();
    float r = srstd;

    size_t base = (size_t)row * D_MODEL;
    float o0 = d0 * r * g[tid]       + b[tid];
    float o1 = d1 * r * g[tid + 256] + b[tid + 256];
    split1(o0, yh + base + tid,       yl + base + tid);
    split1(o1, yh + base + tid + 256, yl + base + tid + 256);
}

// ---------------------------------------------------------------------------
// Fused scan + attention-core kernel (emits attncore bf16 hi/lo)
// ---------------------------------------------------------------------------
__global__ __launch_bounds__(256)
void scan_kernel(const float* __restrict__ allproj, const int* __restrict__ terms,
                 const float* __restrict__ tick, const float* __restrict__ tk,
                 const float* __restrict__ tv, const float* __restrict__ s_prev,
                 bf16* __restrict__ core_h, bf16* __restrict__ core_l)
{
    const int bh = blockIdx.x;
    const int b = bh >> 3, h = bh & 7;
    const int tid = threadIdx.x;
    const int lane = tid & 31, warp = tid >> 5;

    __shared__ float sk[64], sq[64], sv[64], sb[64], sg[64];
    __shared__ float sp[12], socc[8];
    __shared__ float red[9 * 8];
    __shared__ float kdqn[9];
    __shared__ float kvpart[256];
    __shared__ float sterm;

    const int d  = tid >> 2, j = tid & 3;
    const int d2 = tid & 63, r0 = tid >> 6;

    float Kst[8], S, V0, V1;
    #pragma unroll
    for (int r = 0; r < 8; ++r)
        Kst[r] = tk[(((size_t)b * R_ + r) * H_ + h) * 256 + tid];
    S  = s_prev[((size_t)b * H_ + h) * 256 + tid];
    V0 = tv[(((size_t)b * R_ + r0    ) * H_ + h) * 64 + d2];
    V1 = tv[(((size_t)b * R_ + r0 + 4) * H_ + h) * 64 + d2];
    const float tickb = tick[b];

    for (int t = 0; t < T_; ++t) {
        const size_t rowbase = ((size_t)t * B_ + b) * TOTAL_PROJ;
        const float* ap = allproj + rowbase + h * 320;
        if (tid < 64) {
            sk[tid] = ap[tid];
            sq[tid] = ap[64 + tid];
            sv[tid] = ap[128 + tid];
            sb[tid] = ap[192 + tid];
            sg[tid] = ap[256 + tid];
        } else if (tid < 76) {
            sp[tid - 64] = allproj[rowbase + KQV_DIM + h * 12 + (tid - 64)];
        } else if (tid >= 96 && tid < 104) {
            int u = tid - 96;
            float om = -3.14159265358979323846f
                     + (float)u * (6.28318530717958647692f / 7.0f);
            socc[u] = cosf((tickb + (float)(t + 1)) * om);
        } else if (tid == 255) {
            sterm = 1.0f - (float)terms[t * B_ + b];
        }
        __syncthreads();

        const float term = sterm;

        float ke = fmaxf(sk[d], 0.0f) * fmaxf(sp[j], 0.0f);
        float qe = fmaxf(sq[d], 0.0f) * fmaxf(sp[4 + j], 0.0f);
        float ge = sigf(sg[d]) * sigf(sp[8 + j]);
        float kg = ke * ge;
        float dg = (1.0f - ge) * term;
        S = fmaf(dg, S, kg);
        float loc[9];
        #pragma unroll
        for (int r = 0; r < 8; ++r) {
            Kst[r] = fmaf(dg, Kst[r], kg * socc[r]);
            loc[r] = Kst[r] * qe;
        }
        loc[8] = S * qe;

        float bs = sigf(sb[d2]);
        float vg = sv[d2] * bs;
        float db = (1.0f - bs) * term;
        V0 = fmaf(db, V0, vg * socc[r0]);
        V1 = fmaf(db, V1, vg * socc[r0 + 4]);

        #pragma unroll
        for (int v = 0; v < 9; ++v) {
            float x = loc[v];
            x += __shfl_down_sync(0xffffffffu, x, 16);
            x += __shfl_down_sync(0xffffffffu, x, 8);
            x += __shfl_down_sync(0xffffffffu, x, 4);
            x += __shfl_down_sync(0xffffffffu, x, 2);
            x += __shfl_down_sync(0xffffffffu, x, 1);
            if (lane == 0) red[v * 8 + warp] = x;
        }
        __syncthreads();
        if (tid < 9) {
            float s = 0.0f;
            #pragma unroll
            for (int w = 0; w < 8; ++w) s += red[tid * 8 + w];
            kdqn[tid] = (tid == 8) ? (s + 1e-6f) : s;
        }
        __syncthreads();

        kvpart[tid] = V0 * kdqn[r0] + V1 * kdqn[r0 + 4];
        __syncthreads();
        if (tid < 64) {
            float kv = kvpart[tid] + kvpart[64 + tid]
                     + kvpart[128 + tid] + kvpart[192 + tid];
            float val = kv / (16.0f * kdqn[8]);
            size_t idx = ((size_t)t * B_ + b) * D_MODEL + h * 64 + tid;
            split1(val, core_h + idx, core_l + idx);
        }
        __syncthreads();
    }
}

// ---------------------------------------------------------------------------
// GRU stage 1: r = sig(Y0+X0); z = sig(Y1+X1-2); rx = r*x (bf16 hi/lo)
// ---------------------------------------------------------------------------
__global__ __launch_bounds__(256)
void gru_pre(const float* __restrict__ x, const float* __restrict__ Y3,
             const float* __restrict__ X2, bf16* __restrict__ rxh,
             bf16* __restrict__ rxl, float* __restrict__ z, int n)
{
    int idx = blockIdx.x * blockDim.x + threadIdx.x;
    if (idx >= n) return;
    int row = idx >> 9, c = idx & 511;
    size_t yb = (size_t)row * (3 * D_MODEL) + c;
    size_t xb = (size_t)row * (2 * D_MODEL) + c;
    float r = sigf(Y3[yb] + X2[xb]);
    z[idx]  = sigf(Y3[yb + 512] + X2[xb + 512] - 2.0f);
    split1(r * x[idx], rxh + idx, rxl + idx);
}

// ---------------------------------------------------------------------------
// GRU stage 2: h = tanh(Y2 + RX); out = (1-z)*x + z*h  (+ optional hi/lo)
// ---------------------------------------------------------------------------
__global__ __launch_bounds__(256)
void gru_post(const float* __restrict__ x, const float* __restrict__ Y3,
              const float* __restrict__ RX, const float* __restrict__ z,
              float* __restrict__ out, bf16* __restrict__ oh,
              bf16* __restrict__ ol, int n)
{
    int idx = blockIdx.x * blockDim.x + threadIdx.x;
    if (idx >= n) return;
    int row = idx >> 9, c = idx & 511;
    float hh = tanhf(Y3[(size_t)row * (3 * D_MODEL) + 1024 + c] + RX[idx]);
    float zz = z[idx];
    float v = (1.0f - zz) * x[idx] + zz * hh;
    out[idx] = v;
    if (oh) split1(v, oh + idx, ol + idx);
}

// ---------------------------------------------------------------------------
// Launch
// ---------------------------------------------------------------------------
template<typename Tp>
static Tp* symptr(const void* sym) {
    void* p = nullptr;
    cudaGetSymbolAddress(&p, sym);
    return (Tp*)p;
}

extern "C" void kernel_launch(void* const* d_in, const int* in_sizes, int n_in,
                              void* d_out, int out_size)
{
    const float* inputs   = (const float*)d_in[0];
    const int*   terms    = (const int*)  d_in[1];
    const float* tilde_k  = (const float*)d_in[2];
    const float* tilde_v  = (const float*)d_in[3];
    const float* s_prev   = (const float*)d_in[4];
    const float* tick     = (const float*)d_in[5];
    const float* w_proj   = (const float*)d_in[6];
    const float* b_proj   = (const float*)d_in[7];
    const float* w_attn   = (const float*)d_in[8];
    const float* b_attn   = (const float*)d_in[9];
    const float* ln1_g    = (const float*)d_in[10];
    const float* ln1_b    = (const float*)d_in[11];
    const float* ln2_g    = (const float*)d_in[12];
    const float* ln2_b    = (const float*)d_in[13];
    const float* gru1_w   = (const float*)d_in[14];
    const float* gru1_u   = (const float*)d_in[15];
    const float* gru2_w   = (const float*)d_in[16];
    const float* gru2_u   = (const float*)d_in[17];
    const float* ffc_w1   = (const float*)d_in[18];
    const float* ffc_b1   = (const float*)d_in[19];
    const float* ffc_w2   = (const float*)d_in[20];
    const float* ffc_b2   = (const float*)d_in[21];
    float* out = (float*)d_out;

    float* allproj = symptr<float>(g_allproj);
    float* Y3   = symptr<float>(g_Y3);
    float* X2   = symptr<float>(g_X2);
    float* zb   = symptr<float>(g_zb);
    float* RX   = symptr<float>(g_RX);
    float* gate1= symptr<float>(g_gate1);

    bf16 *in_h = symptr<bf16>(g_in_h),  *in_l = symptr<bf16>(g_in_l);
    bf16 *xn_h = symptr<bf16>(g_xn_h),  *xn_l = symptr<bf16>(g_xn_l);
    bf16 *co_h = symptr<bf16>(g_core_h),*co_l = symptr<bf16>(g_core_l);
    bf16 *ar_h = symptr<bf16>(g_arelu_h),*ar_l= symptr<bf16>(g_arelu_l);
    bf16 *rx_h = symptr<bf16>(g_rx_h),  *rx_l = symptr<bf16>(g_rx_l);
    bf16 *g1_h = symptr<bf16>(g_g1_h),  *g1_l = symptr<bf16>(g_g1_l);
    bf16 *ff_h = symptr<bf16>(g_ff_h),  *ff_l = symptr<bf16>(g_ff_l);
    bf16 *hd_h = symptr<bf16>(g_hid_h), *hd_l = symptr<bf16>(g_hid_l);

    bf16 *wp_h = symptr<bf16>(g_wproj_h), *wp_l = symptr<bf16>(g_wproj_l);
    bf16 *wa_h = symptr<bf16>(g_wattn_h), *wa_l = symptr<bf16>(g_wattn_l);
    bf16 *w1w_h= symptr<bf16>(g_g1w_h),   *w1w_l= symptr<bf16>(g_g1w_l);
    bf16 *w1u_h= symptr<bf16>(g_g1u_h),   *w1u_l= symptr<bf16>(g_g1u_l);
    bf16 *w2w_h= symptr<bf16>(g_g2w_h),   *w2w_l= symptr<bf16>(g_g2w_l);
    bf16 *w2u_h= symptr<bf16>(g_g2u_h),   *w2u_l= symptr<bf16>(g_g2u_l);
    bf16 *f1_h = symptr<bf16>(g_fw1_h),   *f1_l = symptr<bf16>(g_fw1_l);
    bf16 *f2_h = symptr<bf16>(g_fw2_h),   *f2_l = symptr<bf16>(g_fw2_l);

    cudaFuncSetAttribute(gemm_tc<0,0>, cudaFuncAttributeMaxDynamicSharedMemorySize, SMEM_GEMM);
    cudaFuncSetAttribute(gemm_tc<1,1>, cudaFuncAttributeMaxDynamicSharedMemorySize, SMEM_GEMM);

    const int n = NTOK * D_MODEL;
    dim3 thr(256);
    const int eg = (n + 255) / 256;
    const int OFF2 = 2 * D_MODEL * D_MODEL;

    // 0) splits: inputs + weights
    split_kernel<<<(n + 255) / 256, thr>>>(inputs, in_h, in_l, n);
    split_kernel<<<(WPROJ_N + 255) / 256, thr>>>(w_proj, wp_h, wp_l, WPROJ_N);
    split_kernel<<<(WATTN_N + 255) / 256, thr>>>(w_attn, wa_h, wa_l, WATTN_N);
    split_kernel<<<(WGRU_N + 255) / 256, thr>>>(gru1_w, w1w_h, w1w_l, WGRU_N);
    split_kernel<<<(WGRU_N + 255) / 256, thr>>>(gru1_u, w1u_h, w1u_l, WGRU_N);
    split_kernel<<<(WGRU_N + 255) / 256, thr>>>(gru2_w, w2w_h, w2w_l, WGRU_N);
    split_kernel<<<(WGRU_N + 255) / 256, thr>>>(gru2_u, w2u_h, w2u_l, WGRU_N);
    split_kernel<<<(WFFC1_N + 255) / 256, thr>>>(ffc_w1, f1_h, f1_l, WFFC1_N);
    split_kernel<<<(WFFC2_N + 255) / 256, thr>>>(ffc_w2, f2_h, f2_l, WFFC2_N);

    // 1) ln1
    ln_kernel<<<NTOK, thr>>>(inputs, ln1_g, ln1_b, xn_h, xn_l);

    // 2) all_proj (4096 x 2656 x 512) -> fp32
    gemm_tc<0,0><<<dim3(21, 32), thr, SMEM_GEMM>>>(
        xn_h, xn_l, wp_h, wp_l, b_proj, allproj, nullptr, nullptr,
        NTOK, TOTAL_PROJ, D_MODEL);

    // 3) scan -> attncore hi/lo
    scan_kernel<<<B_ * H_, thr>>>(allproj, terms, tick, tilde_k, tilde_v,
                                  s_prev, co_h, co_l);

    // 4) attnrelu = relu(core @ w_attn^T + b_attn) -> hi/lo
    gemm_tc<1,1><<<dim3(4, 32), thr, SMEM_GEMM>>>(
        co_h, co_l, wa_h, wa_l, b_attn, nullptr, ar_h, ar_l,
        NTOK, D_MODEL, D_MODEL);

    // 5) GRU1
    gemm_tc<0,0><<<dim3(12, 32), thr, SMEM_GEMM>>>(
        ar_h, ar_l, w1w_h, w1w_l, nullptr, Y3, nullptr, nullptr,
        NTOK, 3 * D_MODEL, D_MODEL);
    gemm_tc<0,0><<<dim3(8, 32), thr, SMEM_GEMM>>>(
        in_h, in_l, w1u_h, w1u_l, nullptr, X2, nullptr, nullptr,
        NTOK, 2 * D_MODEL, D_MODEL);
    gru_pre<<<eg, thr>>>(inputs, Y3, X2, rx_h, rx_l, zb, n);
    gemm_tc<0,0><<<dim3(4, 32), thr, SMEM_GEMM>>>(
        rx_h, rx_l, w1u_h + OFF2, w1u_l + OFF2, nullptr, RX, nullptr, nullptr,
        NTOK, D_MODEL, D_MODEL);
    gru_post<<<eg, thr>>>(inputs, Y3, RX, zb, gate1, g1_h, g1_l, n);

    // 6) ln2
    ln_kernel<<<NTOK, thr>>>(gate1, ln2_g, ln2_b, xn_h, xn_l);

    // 7) FFC
    gemm_tc<1,1><<<dim3(16, 32), thr, SMEM_GEMM>>>(
        xn_h, xn_l, f1_h, f1_l, ffc_b1, nullptr, hd_h, hd_l,
        NTOK, D_FFC, D_MODEL);
    gemm_tc<1,1><<<dim3(4, 32), thr, SMEM_GEMM>>>(
        hd_h, hd_l, f2_h, f2_l, ffc_b2, nullptr, ff_h, ff_l,
        NTOK, D_MODEL, D_FFC);

    // 8) GRU2 -> out
    gemm_tc<0,0><<<dim3(12, 32), thr, SMEM_GEMM>>>(
        ff_h, ff_l, w2w_h, w2w_l, nullptr, Y3, nullptr, nullptr,
        NTOK, 3 * D_MODEL, D_MODEL);
    gemm_tc<0,0><<<dim3(8, 32), thr, SMEM_GEMM>>>(
        g1_h, g1_l, w2u_h, w2u_l, nullptr, X2, nullptr, nullptr,
        NTOK, 2 * D_MODEL, D_MODEL);
    gru_pre<<<eg, thr>>>(gate1, Y3, X2, rx_h, rx_l, zb, n);
    gemm_tc<0,0><<<dim3(4, 32), thr, SMEM_GEMM>>>(
        rx_h, rx_l, w2u_h + OFF2, w2u_l + OFF2, nullptr, RX, nullptr, nullptr,
        NTOK, D_MODEL, D_MODEL);
    gru_post<<<eg, thr>>>(gate1, Y3, RX, zb, out, nullptr, nullptr, n);
}

// round 6
// speedup vs baseline: 3.9082x; 2.2359x over previous
#include <cuda_runtime.h>
#include <cuda_bf16.h>
#include <math.h>
#include <stdint.h>

// Problem constants
#define D_MODEL 512
#define H_ 8
#define HD_ 64
#define ETA_ 4
#define R_ 8
#define D_FFC 2048
#define T_ 128
#define B_ 32
#define NTOK (T_*B_)            // 4096
#define TOTAL_PROJ 2656
#define KQV_DIM 2560

typedef __nv_bfloat16 bf16;

#if defined(__CUDA_ARCH_FEAT_SM103_ALL) || defined(__CUDA_ARCH_FEAT_SM100_ALL)
#define HAS_TCGEN05 1
#else
#define HAS_TCGEN05 0
#endif

// ---------------------------------------------------------------------------
// Scratch (static device arrays; no runtime allocation)
// ---------------------------------------------------------------------------
__device__ float g_allproj[NTOK * TOTAL_PROJ];
__device__ float g_Y3   [NTOK * 3 * D_MODEL];
__device__ float g_X2   [NTOK * 2 * D_MODEL];
__device__ float g_zb   [NTOK * D_MODEL];
__device__ float g_RX   [NTOK * D_MODEL];
__device__ float g_gate1[NTOK * D_MODEL];

// bf16 hi/lo activation pairs (16B aligned for vector access / cp.async)
__device__ __align__(256) bf16 g_in_h   [NTOK * D_MODEL], g_in_l   [NTOK * D_MODEL];
__device__ __align__(256) bf16 g_xn_h   [NTOK * D_MODEL], g_xn_l   [NTOK * D_MODEL];
__device__ __align__(256) bf16 g_core_h [NTOK * D_MODEL], g_core_l [NTOK * D_MODEL];
__device__ __align__(256) bf16 g_arelu_h[NTOK * D_MODEL], g_arelu_l[NTOK * D_MODEL];
__device__ __align__(256) bf16 g_rx_h   [NTOK * D_MODEL], g_rx_l   [NTOK * D_MODEL];
__device__ __align__(256) bf16 g_g1_h   [NTOK * D_MODEL], g_g1_l   [NTOK * D_MODEL];
__device__ __align__(256) bf16 g_ff_h   [NTOK * D_MODEL], g_ff_l   [NTOK * D_MODEL];
__device__ __align__(256) bf16 g_hid_h  [NTOK * D_FFC],   g_hid_l  [NTOK * D_FFC];

// bf16 hi/lo weight pairs
#define WPROJ_N (TOTAL_PROJ * D_MODEL)
#define WATTN_N (D_MODEL * D_MODEL)
#define WGRU_N  (3 * D_MODEL * D_MODEL)
#define WFFC1_N (D_FFC * D_MODEL)
#define WFFC2_N (D_MODEL * D_FFC)
__device__ __align__(256) bf16 g_wproj_h[WPROJ_N], g_wproj_l[WPROJ_N];
__device__ __align__(256) bf16 g_wattn_h[WATTN_N], g_wattn_l[WATTN_N];
__device__ __align__(256) bf16 g_g1w_h[WGRU_N], g_g1w_l[WGRU_N];
__device__ __align__(256) bf16 g_g1u_h[WGRU_N], g_g1u_l[WGRU_N];
__device__ __align__(256) bf16 g_g2w_h[WGRU_N], g_g2w_l[WGRU_N];
__device__ __align__(256) bf16 g_g2u_h[WGRU_N], g_g2u_l[WGRU_N];
__device__ __align__(256) bf16 g_fw1_h[WFFC1_N], g_fw1_l[WFFC1_N];
__device__ __align__(256) bf16 g_fw2_h[WFFC2_N], g_fw2_l[WFFC2_N];

__device__ __forceinline__ float sigf(float x) { return 1.0f / (1.0f + expf(-x)); }

__device__ __forceinline__ void split1(float v, bf16* h, bf16* l) {
    bf16 hv = __float2bfloat16(v);
    *h = hv;
    *l = __float2bfloat16(v - __bfloat162float(hv));
}

// pack 4 floats -> 4 hi bf16 (uint2) + 4 lo bf16 (uint2)
__device__ __forceinline__ void pack4(float4 v, uint2* hp, uint2* lp) {
    bf16 h0 = __float2bfloat16(v.x), h1 = __float2bfloat16(v.y);
    bf16 h2 = __float2bfloat16(v.z), h3 = __float2bfloat16(v.w);
    bf16 l0 = __float2bfloat16(v.x - __bfloat162float(h0));
    bf16 l1 = __float2bfloat16(v.y - __bfloat162float(h1));
    bf16 l2 = __float2bfloat16(v.z - __bfloat162float(h2));
    bf16 l3 = __float2bfloat16(v.w - __bfloat162float(h3));
    __nv_bfloat162 ha = __halves2bfloat162(h0, h1), hb = __halves2bfloat162(h2, h3);
    __nv_bfloat162 la = __halves2bfloat162(l0, l1), lb = __halves2bfloat162(l2, l3);
    uint2 hh, ll;
    hh.x = *reinterpret_cast<uint32_t*>(&ha);
    hh.y = *reinterpret_cast<uint32_t*>(&hb);
    ll.x = *reinterpret_cast<uint32_t*>(&la);
    ll.y = *reinterpret_cast<uint32_t*>(&lb);
    *hp = hh;
    *lp = ll;
}

__device__ __forceinline__ uint32_t smem_u32(const void* p) {
    uint32_t a;
    asm("{ .reg .u64 t; cvta.to.shared.u64 t, %1; cvt.u32.u64 %0, t; }"
        : "=r"(a) : "l"(p));
    return a;
}

// cp.async 16B (with optional zero-fill via src-size)
__device__ __forceinline__ void cp16(uint32_t dst, const void* src) {
    asm volatile("cp.async.cg.shared.global [%0], [%1], 16;"
                 :: "r"(dst), "l"(src));
}
__device__ __forceinline__ void cp16z(uint32_t dst, const void* src, int sz) {
    asm volatile("cp.async.cg.shared.global [%0], [%1], 16, %2;"
                 :: "r"(dst), "l"(src), "r"(sz));
}
__device__ __forceinline__ void cp_commit() {
    asm volatile("cp.async.commit_group;" ::: "memory");
}

// Load one 64-K chunk (Ah/Al/Bh/Bl, each 128x128B SW128-swizzled) into stage sb
__device__ __forceinline__ void load_chunk_cp(
    uint32_t sb, const bf16* Ah, const bf16* Al,
    const bf16* Bh, const bf16* Bl,
    int bm, int bn, int N, int K, int k0, int tid)
{
    #pragma unroll
    for (int p = 0; p < 4; ++p) {
        int id = tid + p * 256;
        int row = id >> 3, grp = id & 7;
        uint32_t boff = (uint32_t)(row * 128 + grp * 16);
        uint32_t sw = boff ^ ((boff >> 3) & 0x70);
        size_t ao = (size_t)(bm + row) * K + k0 + grp * 8;
        cp16(sb + sw,          Ah + ao);
        cp16(sb + 16384 + sw,  Al + ao);
        int brow = bn + row;
        int ok = (brow < N) ? 16 : 0;
        size_t bo = (size_t)(brow < N ? brow : 0) * K + k0 + grp * 8;
        cp16z(sb + 32768 + sw, Bh + bo, ok);
        cp16z(sb + 49152 + sw, Bl + bo, ok);
    }
    cp_commit();
}

#if HAS_TCGEN05
// ---------------------------------------------------------------------------
// tcgen05 PTX helpers (compiled ONLY on the sm_103a/sm_100a pass)
// ---------------------------------------------------------------------------
__device__ __forceinline__ uint32_t elect1() {
    uint32_t r;
    asm volatile("{\n\t.reg .pred p;\n\telect.sync _|p, 0xFFFFFFFF;\n\t"
                 "selp.b32 %0,1,0,p;\n\t}" : "=r"(r));
    return r;
}
__device__ __forceinline__ void tc_alloc(uint32_t saddr, uint32_t ncols) {
    asm volatile("tcgen05.alloc.cta_group::1.sync.aligned.shared::cta.b32 [%0], %1;"
                 :: "r"(saddr), "r"(ncols) : "memory");
}
__device__ __forceinline__ void tc_relinq() {
    asm volatile("tcgen05.relinquish_alloc_permit.cta_group::1.sync.aligned;");
}
__device__ __forceinline__ void tc_dealloc(uint32_t tmem, uint32_t ncols) {
    asm volatile("tcgen05.dealloc.cta_group::1.sync.aligned.b32 %0, %1;"
                 :: "r"(tmem), "r"(ncols));
}
__device__ __forceinline__ void mbar_init(uint32_t mb, uint32_t cnt) {
    asm volatile("mbarrier.init.shared.b64 [%0], %1;" :: "r"(mb), "r"(cnt) : "memory");
}
__device__ __forceinline__ void mbar_wait(uint32_t mb, uint32_t parity) {
    asm volatile("{\n\t.reg .pred P;\n\t"
                 "WL_%=:\n\t"
                 "mbarrier.try_wait.parity.acquire.cta.shared::cta.b64 P, [%0], %1, 0x989680;\n\t"
                 "@!P bra WL_%=;\n\t}"
                 :: "r"(mb), "r"(parity) : "memory");
}
__device__ __forceinline__ void tc_commit(uint32_t mb) {
    asm volatile("tcgen05.commit.cta_group::1.mbarrier::arrive::one.shared::cluster.b64 [%0];"
                 :: "r"(mb) : "memory");
}
__device__ __forceinline__ void fence_async_smem() {
    asm volatile("fence.proxy.async.shared::cta;" ::: "memory");
}
__device__ __forceinline__ void tc_fence_after() {
    asm volatile("tcgen05.fence::after_thread_sync;" ::: "memory");
}
__device__ __forceinline__ void tc_wait_ld() {
    asm volatile("tcgen05.wait::ld.sync.aligned;" ::: "memory");
}
__device__ __forceinline__ void mma_ss(uint32_t d, uint64_t a, uint64_t b,
                                       uint32_t idesc, bool en) {
    uint32_t e = en ? 1u : 0u;
    asm volatile("{\n\t.reg .pred p;\n\tsetp.ne.u32 p, %4, 0;\n\t"
                 "tcgen05.mma.cta_group::1.kind::f16 [%0], %1, %2, %3, "
                 "{%5, %5, %5, %5}, p;\n\t}"
                 :: "r"(d), "l"(a), "l"(b), "r"(idesc), "r"(e), "r"(0u)
                 : "memory");
}
__device__ __forceinline__ void ldtm32(uint32_t* r, uint32_t tmem) {
    asm volatile(
        "tcgen05.ld.sync.aligned.32x32b.x32.b32 "
        "{%0, %1, %2, %3, %4, %5, %6, %7, %8, %9, %10, %11, %12, %13, %14, %15, "
        "%16, %17, %18, %19, %20, %21, %22, %23, %24, %25, %26, %27, %28, %29, %30, %31}, [%32];"
        : "=r"(r[0]), "=r"(r[1]), "=r"(r[2]), "=r"(r[3]),
          "=r"(r[4]), "=r"(r[5]), "=r"(r[6]), "=r"(r[7]),
          "=r"(r[8]), "=r"(r[9]), "=r"(r[10]), "=r"(r[11]),
          "=r"(r[12]), "=r"(r[13]), "=r"(r[14]), "=r"(r[15]),
          "=r"(r[16]), "=r"(r[17]), "=r"(r[18]), "=r"(r[19]),
          "=r"(r[20]), "=r"(r[21]), "=r"(r[22]), "=r"(r[23]),
          "=r"(r[24]), "=r"(r[25]), "=r"(r[26]), "=r"(r[27]),
          "=r"(r[28]), "=r"(r[29]), "=r"(r[30]), "=r"(r[31])
        : "r"(tmem));
}
__device__ __forceinline__ uint64_t mk_desc(uint32_t saddr) {
    const uint64_t base = (uint64_t(2) << 61) | (uint64_t(1) << 46)
                        | (uint64_t(64) << 32) | (uint64_t(1) << 16);
    return base | ((uint64_t)(saddr >> 4) & 0x3FFF);
}
#define IDESC_128 ((1u << 4) | (1u << 7) | (1u << 10) | (16u << 17) | (8u << 24))
#endif // HAS_TCGEN05

// Fallback warp MMA (legal on any sm_80+ target, incl. plain sm_103)
__device__ __forceinline__ void mma16816(float* d, uint32_t a0, uint32_t a1,
                                         uint32_t a2, uint32_t a3,
                                         uint32_t b0, uint32_t b1) {
    asm volatile(
        "mma.sync.aligned.m16n8k16.row.col.f32.bf16.bf16.f32 "
        "{%0,%1,%2,%3}, {%4,%5,%6,%7}, {%8,%9}, {%0,%1,%2,%3};"
        : "+f"(d[0]), "+f"(d[1]), "+f"(d[2]), "+f"(d[3])
        : "r"(a0), "r"(a1), "r"(a2), "r"(a3), "r"(b0), "r"(b1));
}

// ---------------------------------------------------------------------------
// bf16-split GEMM: C[M,N] = act(A @ B^T + bias). Tile 128x128, K-chunk 64.
// 2-stage cp.async pipeline (64KB stages). tcgen05 SS MMA on sm_103a pass;
// mma.sync fallback elsewhere. Coalesced transposed epilogue via smem.
// ---------------------------------------------------------------------------
#define STAGE_BYTES 65536
#define SMEM_GEMM (1024 + 2 * STAGE_BYTES + 1024)

template<int ACT, int OUTMODE>
__global__ __launch_bounds__(256)
void gemm_tc(const bf16* __restrict__ Ah, const bf16* __restrict__ Al,
             const bf16* __restrict__ Bh, const bf16* __restrict__ Bl,
             const float* __restrict__ bias,
             float* __restrict__ Cf, bf16* __restrict__ Ch, bf16* __restrict__ Cl,
             int M, int N, int K)
{
    extern __shared__ char dsm[];
    const uint32_t sraw = smem_u32(dsm);
    const uint32_t tile0 = (sraw + 1024u) & ~1023u;
    const uint32_t off0 = tile0 - sraw;

    const int tid = threadIdx.x;
    const int wid = tid >> 5, lid = tid & 31;
    const int bm = blockIdx.y * 128;
    const int bn = blockIdx.x * 128;
    char* smc = dsm;
    const int nk = K >> 6;

#if HAS_TCGEN05
    const uint32_t mb0 = sraw + 8, mb1 = sraw + 16;

    if (wid == 0) { tc_alloc(sraw, 128); tc_relinq(); }
    if (tid == 0) { mbar_init(mb0, 1); mbar_init(mb1, 1); }
    __syncthreads();
    uint32_t tmem;
    asm volatile("ld.shared.b32 %0, [%1];" : "=r"(tmem) : "r"(sraw));

    load_chunk_cp(tile0, Ah, Al, Bh, Bl, bm, bn, N, K, 0, tid);

    int ph0 = 0, ph1 = 0;
    for (int k = 0; k < nk; ++k) {
        const int s = k & 1;
        if (k + 1 < nk) {
            if (k >= 1) {
                if (((k + 1) & 1) == 0) { mbar_wait(mb0, ph0); ph0 ^= 1; }
                else                    { mbar_wait(mb1, ph1); ph1 ^= 1; }
            }
            load_chunk_cp(tile0 + ((k + 1) & 1) * STAGE_BYTES,
                          Ah, Al, Bh, Bl, bm, bn, N, K, (k + 1) * 64, tid);
            asm volatile("cp.async.wait_group 1;" ::: "memory");
        } else {
            asm volatile("cp.async.wait_group 0;" ::: "memory");
        }
        fence_async_smem();
        __syncthreads();

        if (wid == 0) {
            if (elect1()) {
                uint32_t base = tile0 + s * STAGE_BYTES;
                uint64_t dah = mk_desc(base);
                uint64_t dal = mk_desc(base + 16384);
                uint64_t dbh = mk_desc(base + 32768);
                uint64_t dbl = mk_desc(base + 49152);
                #pragma unroll
                for (int ks = 0; ks < 4; ++ks) {
                    uint64_t o = (uint64_t)(ks * 2);
                    bool en0 = (k > 0) || (ks > 0);
                    mma_ss(tmem, dah + o, dbh + o, IDESC_128, en0);
                    mma_ss(tmem, dah + o, dbl + o, IDESC_128, true);
                    mma_ss(tmem, dal + o, dbh + o, IDESC_128, true);
                }
                tc_commit(s == 0 ? mb0 : mb1);
            }
        }
    }
    // final MMA completion
    if (((nk - 1) & 1) == 0) mbar_wait(mb0, ph0);
    else                     mbar_wait(mb1, ph1);
    tc_fence_after();
    __syncthreads();

    // Coalesced epilogue: LDTM -> smem (pad 33) -> lane=col global stores
    float* sf = (float*)(smc + off0);
    #pragma unroll
    for (int nb = 0; nb < 4; ++nb) {
        if (wid < 4) {
            uint32_t dr[32];
            ldtm32(dr, tmem + nb * 32);
            tc_wait_ld();
            int mrow = wid * 32 + lid;
            #pragma unroll
            for (int c = 0; c < 32; ++c) sf[mrow * 33 + c] = __uint_as_float(dr[c]);
        }
        __syncthreads();
        int cb = bn + nb * 32;
        if (cb < N) {
            int col = cb + lid;
            float bv = bias ? bias[col] : 0.0f;
            int rbase = (tid >> 5) * 16;
            #pragma unroll
            for (int rr = 0; rr < 16; ++rr) {
                int row = rbase + rr;
                float v = sf[row * 33 + lid] + bv;
                if (ACT) v = fmaxf(v, 0.0f);
                size_t idx = (size_t)(bm + row) * N + col;
                if (OUTMODE == 0) {
                    Cf[idx] = v;
                } else {
                    bf16 h = __float2bfloat16(v);
                    Ch[idx] = h;
                    Cl[idx] = __float2bfloat16(v - __bfloat162float(h));
                }
            }
        }
        __syncthreads();
    }
    if (wid == 0) tc_dealloc(tmem, 128);

#else  // ------------------- mma.sync fallback path -------------------------
    const int wm0 = (wid >> 2) * 64;   // warp grid 2(M) x 4(N)
    const int wn0 = (wid & 3) * 32;
    const int g = lid >> 2, tg = lid & 3;

    float acc[4][4][4];
    #pragma unroll
    for (int a = 0; a < 4; ++a)
        #pragma unroll
        for (int b = 0; b < 4; ++b)
            #pragma unroll
            for (int c = 0; c < 4; ++c) acc[a][b][c] = 0.0f;

    load_chunk_cp(tile0, Ah, Al, Bh, Bl, bm, bn, N, K, 0, tid);

    for (int k = 0; k < nk; ++k) {
        const uint32_t oS = off0 + (uint32_t)(k & 1) * STAGE_BYTES;
        if (k + 1 < nk) {
            load_chunk_cp(tile0 + ((k + 1) & 1) * STAGE_BYTES,
                          Ah, Al, Bh, Bl, bm, bn, N, K, (k + 1) * 64, tid);
            asm volatile("cp.async.wait_group 1;" ::: "memory");
        } else {
            asm volatile("cp.async.wait_group 0;" ::: "memory");
        }
        __syncthreads();

        const uint32_t oA_h = oS, oA_l = oS + 16384;
        const uint32_t oB_h = oS + 32768, oB_l = oS + 49152;

        #pragma unroll
        for (int ks = 0; ks < 4; ++ks) {
            const uint32_t kb = (uint32_t)(ks * 32 + tg * 4);
            uint32_t bh0[4], bh1[4], bl0[4], bl1[4];
            #pragma unroll
            for (int nt = 0; nt < 4; ++nt) {
                uint32_t row = (uint32_t)(wn0 + nt * 8 + g);
                uint32_t o1 = row * 128 + kb;
                uint32_t o2 = o1 + 16;
                uint32_t s1 = o1 ^ ((o1 >> 3) & 0x70);
                uint32_t s2 = o2 ^ ((o2 >> 3) & 0x70);
                bh0[nt] = *(const uint32_t*)(smc + oB_h + s1);
                bh1[nt] = *(const uint32_t*)(smc + oB_h + s2);
                bl0[nt] = *(const uint32_t*)(smc + oB_l + s1);
                bl1[nt] = *(const uint32_t*)(smc + oB_l + s2);
            }
            #pragma unroll
            for (int mt = 0; mt < 4; ++mt) {
                uint32_t r0 = (uint32_t)(wm0 + mt * 16 + g);
                uint32_t o_r0c0 = r0 * 128 + kb;
                uint32_t o_r8c0 = o_r0c0 + 8 * 128;
                uint32_t o_r0c8 = o_r0c0 + 16;
                uint32_t o_r8c8 = o_r8c0 + 16;
                uint32_t s00 = o_r0c0 ^ ((o_r0c0 >> 3) & 0x70);
                uint32_t s80 = o_r8c0 ^ ((o_r8c0 >> 3) & 0x70);
                uint32_t s08 = o_r0c8 ^ ((o_r0c8 >> 3) & 0x70);
                uint32_t s88 = o_r8c8 ^ ((o_r8c8 >> 3) & 0x70);
                uint32_t ah0 = *(const uint32_t*)(smc + oA_h + s00);
                uint32_t ah1 = *(const uint32_t*)(smc + oA_h + s80);
                uint32_t ah2 = *(const uint32_t*)(smc + oA_h + s08);
                uint32_t ah3 = *(const uint32_t*)(smc + oA_h + s88);
                uint32_t al0 = *(const uint32_t*)(smc + oA_l + s00);
                uint32_t al1 = *(const uint32_t*)(smc + oA_l + s80);
                uint32_t al2 = *(const uint32_t*)(smc + oA_l + s08);
                uint32_t al3 = *(const uint32_t*)(smc + oA_l + s88);
                #pragma unroll
                for (int nt = 0; nt < 4; ++nt) {
                    mma16816(acc[mt][nt], ah0, ah1, ah2, ah3, bh0[nt], bh1[nt]);
                    mma16816(acc[mt][nt], ah0, ah1, ah2, ah3, bl0[nt], bl1[nt]);
                    mma16816(acc[mt][nt], al0, al1, al2, al3, bh0[nt], bh1[nt]);
                }
            }
        }
        __syncthreads();
    }

    #pragma unroll
    for (int mt = 0; mt < 4; ++mt) {
        #pragma unroll
        for (int nt = 0; nt < 4; ++nt) {
            int r0 = bm + wm0 + mt * 16 + g;
            int c0 = bn + wn0 + nt * 8 + tg * 2;
            #pragma unroll
            for (int half = 0; half < 2; ++half) {
                int row = r0 + half * 8;
                #pragma unroll
                for (int cc = 0; cc < 2; ++cc) {
                    int col = c0 + cc;
                    if (col < N) {
                        float v = acc[mt][nt][half * 2 + cc];
                        if (bias) v += bias[col];
                        if (ACT) v = fmaxf(v, 0.0f);
                        size_t idx = (size_t)row * N + col;
                        if (OUTMODE == 0) {
                            Cf[idx] = v;
                        } else {
                            bf16 h = __float2bfloat16(v);
                            Ch[idx] = h;
                            Cl[idx] = __float2bfloat16(v - __bfloat162float(h));
                        }
                    }
                }
            }
        }
    }
#endif
}

// ---------------------------------------------------------------------------
// Split fp32 -> bf16 hi/lo (vectorized: float4 in, 2x uint2 out)
// ---------------------------------------------------------------------------
__global__ __launch_bounds__(256)
void split_kernel(const float4* __restrict__ x, uint2* __restrict__ h,
                  uint2* __restrict__ l, int n4)
{
    int i = blockIdx.x * 256 + threadIdx.x;
    if (i < n4) pack4(x[i], h + i, l + i);
}

// ---------------------------------------------------------------------------
// LayerNorm: one block per row of 512, emits bf16 hi/lo
// ---------------------------------------------------------------------------
__global__ __launch_bounds__(256)
void ln_kernel(const float* __restrict__ x, const float* __restrict__ g,
               const float* __restrict__ b, bf16* __restrict__ yh,
               bf16* __restrict__ yl)
{
    __shared__ float rbuf[8];
    __shared__ float smean, srstd;
    const int row = blockIdx.x;
    const int tid = threadIdx.x;
    const int lane = tid & 31, warp = tid >> 5;
    const float* xr = x + (size_t)row * D_MODEL;

    float v0 = xr[tid], v1 = xr[tid + 256];

    float s = v0 + v1;
    #pragma unroll
    for (int o = 16; o; o >>= 1) s += __shfl_down_sync(0xffffffffu, s, o);
    if (!lane) rbuf[warp] = s;
    __syncthreads();
    if (warp == 0) {
        float t = (lane < 8) ? rbuf[lane] : 0.0f;
        #pragma unroll
        for (int o = 4; o; o >>= 1) t += __shfl_down_sync(0xffffffffu, t, o);
        if (!lane) smean = t * (1.0f / D_MODEL);
    }
    __syncthreads();
    float m = smean;

    float d0 = v0 - m, d1 = v1 - m;
    float sv = d0 * d0 + d1 * d1;
    #pragma unroll
    for (int o = 16; o; o >>= 1) sv += __shfl_down_sync(0xffffffffu, sv, o);
    if (!lane) rbuf[warp] = sv;
    __syncthreads();
    if (warp == 0) {
        float t = (lane < 8) ? rbuf[lane] : 0.0f;
        #pragma unroll
        for (int o = 4; o; o >>= 1) t += __shfl_down_sync(0xffffffffu, t, o);
        if (!lane) srstd = rsqrtf(t * (1.0f / D_MODEL) + 1e-5f);
    }
    __syncthreads();
    float r = srstd;

    size_t base = (size_t)row * D_MODEL;
    float o0 = d0 * r * g[tid]       + b[tid];
    float o1 = d1 * r * g[tid + 256] + b[tid + 256];
    split1(o0, yh + base + tid,       yl + base + tid);
    split1(o1, yh + base + tid + 256, yl + base + tid + 256);
}

// ---------------------------------------------------------------------------
// Fused scan + attention-core kernel (emits attncore bf16 hi/lo)
// ---------------------------------------------------------------------------
__global__ __launch_bounds__(256)
void scan_kernel(const float* __restrict__ allproj, const int* __restrict__ terms,
                 const float* __restrict__ tick, const float* __restrict__ tk,
                 const float* __restrict__ tv, const float* __restrict__ s_prev,
                 bf16* __restrict__ core_h, bf16* __restrict__ core_l)
{
    const int bh = blockIdx.x;
    const int b = bh >> 3, h = bh & 7;
    const int tid = threadIdx.x;
    const int lane = tid & 31, warp = tid >> 5;

    __shared__ float sk[64], sq[64], sv[64], sb[64], sg[64];
    __shared__ float sp[12], socc[8];
    __shared__ float red[9 * 8];
    __shared__ float kdqn[9];
    __shared__ float kvpart[256];
    __shared__ float sterm;

    const int d  = tid >> 2, j = tid & 3;
    const int d2 = tid & 63, r0 = tid >> 6;

    float Kst[8], S, V0, V1;
    #pragma unroll
    for (int r = 0; r < 8; ++r)
        Kst[r] = tk[(((size_t)b * R_ + r) * H_ + h) * 256 + tid];
    S  = s_prev[((size_t)b * H_ + h) * 256 + tid];
    V0 = tv[(((size_t)b * R_ + r0    ) * H_ + h) * 64 + d2];
    V1 = tv[(((size_t)b * R_ + r0 + 4) * H_ + h) * 64 + d2];
    const float tickb = tick[b];

    for (int t = 0; t < T_; ++t) {
        const size_t rowbase = ((size_t)t * B_ + b) * TOTAL_PROJ;
        const float* ap = allproj + rowbase + h * 320;
        if (tid < 64) {
            sk[tid] = ap[tid];
            sq[tid] = ap[64 + tid];
            sv[tid] = ap[128 + tid];
            sb[tid] = ap[192 + tid];
            sg[tid] = ap[256 + tid];
        } else if (tid < 76) {
            sp[tid - 64] = allproj[rowbase + KQV_DIM + h * 12 + (tid - 64)];
        } else if (tid >= 96 && tid < 104) {
            int u = tid - 96;
            float om = -3.14159265358979323846f
                     + (float)u * (6.28318530717958647692f / 7.0f);
            socc[u] = cosf((tickb + (float)(t + 1)) * om);
        } else if (tid == 255) {
            sterm = 1.0f - (float)terms[t * B_ + b];
        }
        __syncthreads();

        const float term = sterm;

        float ke = fmaxf(sk[d], 0.0f) * fmaxf(sp[j], 0.0f);
        float qe = fmaxf(sq[d], 0.0f) * fmaxf(sp[4 + j], 0.0f);
        float ge = sigf(sg[d]) * sigf(sp[8 + j]);
        float kg = ke * ge;
        float dg = (1.0f - ge) * term;
        S = fmaf(dg, S, kg);
        float loc[9];
        #pragma unroll
        for (int r = 0; r < 8; ++r) {
            Kst[r] = fmaf(dg, Kst[r], kg * socc[r]);
            loc[r] = Kst[r] * qe;
        }
        loc[8] = S * qe;

        float bs = sigf(sb[d2]);
        float vg = sv[d2] * bs;
        float db = (1.0f - bs) * term;
        V0 = fmaf(db, V0, vg * socc[r0]);
        V1 = fmaf(db, V1, vg * socc[r0 + 4]);

        #pragma unroll
        for (int v = 0; v < 9; ++v) {
            float x = loc[v];
            x += __shfl_down_sync(0xffffffffu, x, 16);
            x += __shfl_down_sync(0xffffffffu, x, 8);
            x += __shfl_down_sync(0xffffffffu, x, 4);
            x += __shfl_down_sync(0xffffffffu, x, 2);
            x += __shfl_down_sync(0xffffffffu, x, 1);
            if (lane == 0) red[v * 8 + warp] = x;
        }
        __syncthreads();
        if (tid < 9) {
            float s = 0.0f;
            #pragma unroll
            for (int w = 0; w < 8; ++w) s += red[tid * 8 + w];
            kdqn[tid] = (tid == 8) ? (s + 1e-6f) : s;
        }
        __syncthreads();

        kvpart[tid] = V0 * kdqn[r0] + V1 * kdqn[r0 + 4];
        __syncthreads();
        if (tid < 64) {
            float kv = kvpart[tid] + kvpart[64 + tid]
                     + kvpart[128 + tid] + kvpart[192 + tid];
            float val = kv / (16.0f * kdqn[8]);
            size_t idx = ((size_t)t * B_ + b) * D_MODEL + h * 64 + tid;
            split1(val, core_h + idx, core_l + idx);
        }
        __syncthreads();
    }
}

// ---------------------------------------------------------------------------
// GRU stage 1 (vectorized): r = sig(Y0+X0); z = sig(Y1+X1-2); rx = r*x
// ---------------------------------------------------------------------------
__global__ __launch_bounds__(256)
void gru_pre(const float4* __restrict__ x, const float* __restrict__ Y3,
             const float* __restrict__ X2, uint2* __restrict__ rxh,
             uint2* __restrict__ rxl, float4* __restrict__ z, int n4)
{
    int i = blockIdx.x * 256 + threadIdx.x;
    if (i >= n4) return;
    int row = i >> 7, c = (i & 127) * 4;
    const float4 y0 = *(const float4*)&Y3[(size_t)row * 1536 + c];
    const float4 y1 = *(const float4*)&Y3[(size_t)row * 1536 + 512 + c];
    const float4 x0 = *(const float4*)&X2[(size_t)row * 1024 + c];
    const float4 x1 = *(const float4*)&X2[(size_t)row * 1024 + 512 + c];
    float4 xv = x[i];
    float4 zz;
    zz.x = sigf(y1.x + x1.x - 2.0f);
    zz.y = sigf(y1.y + x1.y - 2.0f);
    zz.z = sigf(y1.z + x1.z - 2.0f);
    zz.w = sigf(y1.w + x1.w - 2.0f);
    float4 rx;
    rx.x = sigf(y0.x + x0.x) * xv.x;
    rx.y = sigf(y0.y + x0.y) * xv.y;
    rx.z = sigf(y0.z + x0.z) * xv.z;
    rx.w = sigf(y0.w + x0.w) * xv.w;
    z[i] = zz;
    pack4(rx, rxh + i, rxl + i);
}

// ---------------------------------------------------------------------------
// GRU stage 2 (vectorized): h = tanh(Y2 + RX); out = (1-z)*x + z*h
// ---------------------------------------------------------------------------
__global__ __launch_bounds__(256)
void gru_post(const float4* __restrict__ x, const float* __restrict__ Y3,
              const float4* __restrict__ RX, const float4* __restrict__ z,
              float4* __restrict__ out, uint2* __restrict__ oh,
              uint2* __restrict__ ol, int n4)
{
    int i = blockIdx.x * 256 + threadIdx.x;
    if (i >= n4) return;
    int row = i >> 7, c = (i & 127) * 4;
    const float4 y2 = *(const float4*)&Y3[(size_t)row * 1536 + 1024 + c];
    float4 rxv = RX[i], zz = z[i], xv = x[i];
    float4 v;
    v.x = (1.0f - zz.x) * xv.x + zz.x * tanhf(y2.x + rxv.x);
    v.y = (1.0f - zz.y) * xv.y + zz.y * tanhf(y2.y + rxv.y);
    v.z = (1.0f - zz.z) * xv.z + zz.z * tanhf(y2.z + rxv.z);
    v.w = (1.0f - zz.w) * xv.w + zz.w * tanhf(y2.w + rxv.w);
    out[i] = v;
    if (oh) pack4(v, oh + i, ol + i);
}

// ---------------------------------------------------------------------------
// Launch
// ---------------------------------------------------------------------------
template<typename Tp>
static Tp* symptr(const void* sym) {
    void* p = nullptr;
    cudaGetSymbolAddress(&p, sym);
    return (Tp*)p;
}

extern "C" void kernel_launch(void* const* d_in, const int* in_sizes, int n_in,
                              void* d_out, int out_size)
{
    const float* inputs   = (const float*)d_in[0];
    const int*   terms    = (const int*)  d_in[1];
    const float* tilde_k  = (const float*)d_in[2];
    const float* tilde_v  = (const float*)d_in[3];
    const float* s_prev   = (const float*)d_in[4];
    const float* tick     = (const float*)d_in[5];
    const float* w_proj   = (const float*)d_in[6];
    const float* b_proj   = (const float*)d_in[7];
    const float* w_attn   = (const float*)d_in[8];
    const float* b_attn   = (const float*)d_in[9];
    const float* ln1_g    = (const float*)d_in[10];
    const float* ln1_b    = (const float*)d_in[11];
    const float* ln2_g    = (const float*)d_in[12];
    const float* ln2_b    = (const float*)d_in[13];
    const float* gru1_w   = (const float*)d_in[14];
    const float* gru1_u   = (const float*)d_in[15];
    const float* gru2_w   = (const float*)d_in[16];
    const float* gru2_u   = (const float*)d_in[17];
    const float* ffc_w1   = (const float*)d_in[18];
    const float* ffc_b1   = (const float*)d_in[19];
    const float* ffc_w2   = (const float*)d_in[20];
    const float* ffc_b2   = (const float*)d_in[21];
    float* out = (float*)d_out;

    float* allproj = symptr<float>(g_allproj);
    float* Y3   = symptr<float>(g_Y3);
    float* X2   = symptr<float>(g_X2);
    float* zb   = symptr<float>(g_zb);
    float* RX   = symptr<float>(g_RX);
    float* gate1= symptr<float>(g_gate1);

    bf16 *in_h = symptr<bf16>(g_in_h),  *in_l = symptr<bf16>(g_in_l);
    bf16 *xn_h = symptr<bf16>(g_xn_h),  *xn_l = symptr<bf16>(g_xn_l);
    bf16 *co_h = symptr<bf16>(g_core_h),*co_l = symptr<bf16>(g_core_l);
    bf16 *ar_h = symptr<bf16>(g_arelu_h),*ar_l= symptr<bf16>(g_arelu_l);
    bf16 *rx_h = symptr<bf16>(g_rx_h),  *rx_l = symptr<bf16>(g_rx_l);
    bf16 *g1_h = symptr<bf16>(g_g1_h),  *g1_l = symptr<bf16>(g_g1_l);
    bf16 *ff_h = symptr<bf16>(g_ff_h),  *ff_l = symptr<bf16>(g_ff_l);
    bf16 *hd_h = symptr<bf16>(g_hid_h), *hd_l = symptr<bf16>(g_hid_l);

    bf16 *wp_h = symptr<bf16>(g_wproj_h), *wp_l = symptr<bf16>(g_wproj_l);
    bf16 *wa_h = symptr<bf16>(g_wattn_h), *wa_l = symptr<bf16>(g_wattn_l);
    bf16 *w1w_h= symptr<bf16>(g_g1w_h),   *w1w_l= symptr<bf16>(g_g1w_l);
    bf16 *w1u_h= symptr<bf16>(g_g1u_h),   *w1u_l= symptr<bf16>(g_g1u_l);
    bf16 *w2w_h= symptr<bf16>(g_g2w_h),   *w2w_l= symptr<bf16>(g_g2w_l);
    bf16 *w2u_h= symptr<bf16>(g_g2u_h),   *w2u_l= symptr<bf16>(g_g2u_l);
    bf16 *f1_h = symptr<bf16>(g_fw1_h),   *f1_l = symptr<bf16>(g_fw1_l);
    bf16 *f2_h = symptr<bf16>(g_fw2_h),   *f2_l = symptr<bf16>(g_fw2_l);

    cudaFuncSetAttribute(gemm_tc<0,0>, cudaFuncAttributeMaxDynamicSharedMemorySize, SMEM_GEMM);
    cudaFuncSetAttribute(gemm_tc<1,1>, cudaFuncAttributeMaxDynamicSharedMemorySize, SMEM_GEMM);

    const int n = NTOK * D_MODEL;
    const int n4 = n / 4;
    dim3 thr(256);
    const int eg4 = (n4 + 255) / 256;
    const int OFF2 = 2 * D_MODEL * D_MODEL;

    #define SPLIT(src, dh, dl, cnt) \
        split_kernel<<<((cnt)/4 + 255) / 256, thr>>>( \
            (const float4*)(src), (uint2*)(dh), (uint2*)(dl), (cnt)/4)

    // Launch order arranged so the proj GEMM is launch index 5 (ncu -s 5 -c 1).
    SPLIT(inputs, in_h, in_l, n);                             // 0
    ln_kernel<<<NTOK, thr>>>(inputs, ln1_g, ln1_b, xn_h, xn_l);// 1
    SPLIT(w_proj, wp_h, wp_l, WPROJ_N);                       // 2
    SPLIT(gru1_w, w1w_h, w1w_l, WGRU_N);                      // 3
    SPLIT(gru1_u, w1u_h, w1u_l, WGRU_N);                      // 4
    gemm_tc<0,0><<<dim3(21, 32), thr, SMEM_GEMM>>>(           // 5  <-- profiled
        xn_h, xn_l, wp_h, wp_l, b_proj, allproj, nullptr, nullptr,
        NTOK, TOTAL_PROJ, D_MODEL);
    SPLIT(w_attn, wa_h, wa_l, WATTN_N);                       // 6
    SPLIT(gru2_w, w2w_h, w2w_l, WGRU_N);                      // 7
    SPLIT(gru2_u, w2u_h, w2u_l, WGRU_N);                      // 8
    SPLIT(ffc_w1, f1_h, f1_l, WFFC1_N);                       // 9
    SPLIT(ffc_w2, f2_h, f2_l, WFFC2_N);                       // 10

    // scan -> attncore hi/lo
    scan_kernel<<<B_ * H_, thr>>>(allproj, terms, tick, tilde_k, tilde_v,
                                  s_prev, co_h, co_l);

    // attnrelu = relu(core @ w_attn^T + b_attn) -> hi/lo
    gemm_tc<1,1><<<dim3(4, 32), thr, SMEM_GEMM>>>(
        co_h, co_l, wa_h, wa_l, b_attn, nullptr, ar_h, ar_l,
        NTOK, D_MODEL, D_MODEL);

    // GRU1
    gemm_tc<0,0><<<dim3(12, 32), thr, SMEM_GEMM>>>(
        ar_h, ar_l, w1w_h, w1w_l, nullptr, Y3, nullptr, nullptr,
        NTOK, 3 * D_MODEL, D_MODEL);
    gemm_tc<0,0><<<dim3(8, 32), thr, SMEM_GEMM>>>(
        in_h, in_l, w1u_h, w1u_l, nullptr, X2, nullptr, nullptr,
        NTOK, 2 * D_MODEL, D_MODEL);
    gru_pre<<<eg4, thr>>>((const float4*)inputs, Y3, X2,
                          (uint2*)rx_h, (uint2*)rx_l, (float4*)zb, n4);
    gemm_tc<0,0><<<dim3(4, 32), thr, SMEM_GEMM>>>(
        rx_h, rx_l, w1u_h + OFF2, w1u_l + OFF2, nullptr, RX, nullptr, nullptr,
        NTOK, D_MODEL, D_MODEL);
    gru_post<<<eg4, thr>>>((const float4*)inputs, Y3, (const float4*)RX,
                           (const float4*)zb, (float4*)gate1,
                           (uint2*)g1_h, (uint2*)g1_l, n4);

    // ln2
    ln_kernel<<<NTOK, thr>>>(gate1, ln2_g, ln2_b, xn_h, xn_l);

    // FFC
    gemm_tc<1,1><<<dim3(16, 32), thr, SMEM_GEMM>>>(
        xn_h, xn_l, f1_h, f1_l, ffc_b1, nullptr, hd_h, hd_l,
        NTOK, D_FFC, D_MODEL);
    gemm_tc<1,1><<<dim3(4, 32), thr, SMEM_GEMM>>>(
        hd_h, hd_l, f2_h, f2_l, ffc_b2, nullptr, ff_h, ff_l,
        NTOK, D_MODEL, D_FFC);

    // GRU2 -> out
    gemm_tc<0,0><<<dim3(12, 32), thr, SMEM_GEMM>>>(
        ff_h, ff_l, w2w_h, w2w_l, nullptr, Y3, nullptr, nullptr,
        NTOK, 3 * D_MODEL, D_MODEL);
    gemm_tc<0,0><<<dim3(8, 32), thr, SMEM_GEMM>>>(
        g1_h, g1_l, w2u_h, w2u_l, nullptr, X2, nullptr, nullptr,
        NTOK, 2 * D_MODEL, D_MODEL);
    gru_pre<<<eg4, thr>>>((const float4*)gate1, Y3, X2,
                          (uint2*)rx_h, (uint2*)rx_l, (float4*)zb, n4);
    gemm_tc<0,0><<<dim3(4, 32), thr, SMEM_GEMM>>>(
        rx_h, rx_l, w2u_h + OFF2, w2u_l + OFF2, nullptr, RX, nullptr, nullptr,
        NTOK, D_MODEL, D_MODEL);
    gru_post<<<eg4, thr>>>((const float4*)gate1, Y3, (const float4*)RX,
                           (const float4*)zb, (float4*)out,
                           nullptr, nullptr, n4);
    #undef SPLIT
}

// round 7
// speedup vs baseline: 3.9107x; 1.0006x over previous
#include <cuda_runtime.h>
#include <cuda_bf16.h>
#include <math.h>
#include <stdint.h>

// Problem constants
#define D_MODEL 512
#define H_ 8
#define HD_ 64
#define ETA_ 4
#define R_ 8
#define D_FFC 2048
#define T_ 128
#define B_ 32
#define NTOK (T_*B_)            // 4096
#define TOTAL_PROJ 2656
#define KQV_DIM 2560

typedef __nv_bfloat16 bf16;

#if defined(__CUDA_ARCH_FEAT_SM103_ALL) || defined(__CUDA_ARCH_FEAT_SM100_ALL)
#define HAS_TCGEN05 1
#else
#define HAS_TCGEN05 0
#endif

// ---------------------------------------------------------------------------
// Scratch (static device arrays; no runtime allocation)
// ---------------------------------------------------------------------------
__device__ float g_allproj[NTOK * TOTAL_PROJ];
__device__ float g_Y3   [NTOK * 3 * D_MODEL];
__device__ float g_X2   [NTOK * 2 * D_MODEL];
__device__ float g_zb   [NTOK * D_MODEL];
__device__ float g_RX   [NTOK * D_MODEL];
__device__ float g_gate1[NTOK * D_MODEL];

// bf16 hi/lo activation pairs
__device__ __align__(256) bf16 g_in_h   [NTOK * D_MODEL], g_in_l   [NTOK * D_MODEL];
__device__ __align__(256) bf16 g_xn_h   [NTOK * D_MODEL], g_xn_l   [NTOK * D_MODEL];
__device__ __align__(256) bf16 g_core_h [NTOK * D_MODEL], g_core_l [NTOK * D_MODEL];
__device__ __align__(256) bf16 g_arelu_h[NTOK * D_MODEL], g_arelu_l[NTOK * D_MODEL];
__device__ __align__(256) bf16 g_rx_h   [NTOK * D_MODEL], g_rx_l   [NTOK * D_MODEL];
__device__ __align__(256) bf16 g_g1_h   [NTOK * D_MODEL], g_g1_l   [NTOK * D_MODEL];
__device__ __align__(256) bf16 g_ff_h   [NTOK * D_MODEL], g_ff_l   [NTOK * D_MODEL];
__device__ __align__(256) bf16 g_hid_h  [NTOK * D_FFC],   g_hid_l  [NTOK * D_FFC];

// bf16 hi/lo weight pairs
#define WPROJ_N (TOTAL_PROJ * D_MODEL)
#define WATTN_N (D_MODEL * D_MODEL)
#define WGRU_N  (3 * D_MODEL * D_MODEL)
#define WFFC1_N (D_FFC * D_MODEL)
#define WFFC2_N (D_MODEL * D_FFC)
__device__ __align__(256) bf16 g_wproj_h[WPROJ_N], g_wproj_l[WPROJ_N];
__device__ __align__(256) bf16 g_wattn_h[WATTN_N], g_wattn_l[WATTN_N];
__device__ __align__(256) bf16 g_g1w_h[WGRU_N], g_g1w_l[WGRU_N];
__device__ __align__(256) bf16 g_g1u_h[WGRU_N], g_g1u_l[WGRU_N];
__device__ __align__(256) bf16 g_g2w_h[WGRU_N], g_g2w_l[WGRU_N];
__device__ __align__(256) bf16 g_g2u_h[WGRU_N], g_g2u_l[WGRU_N];
__device__ __align__(256) bf16 g_fw1_h[WFFC1_N], g_fw1_l[WFFC1_N];
__device__ __align__(256) bf16 g_fw2_h[WFFC2_N], g_fw2_l[WFFC2_N];

__device__ __forceinline__ float sigf(float x) { return 1.0f / (1.0f + expf(-x)); }

__device__ __forceinline__ void split1(float v, bf16* h, bf16* l) {
    bf16 hv = __float2bfloat16(v);
    *h = hv;
    *l = __float2bfloat16(v - __bfloat162float(hv));
}

__device__ __forceinline__ void pack4(float4 v, uint2* hp, uint2* lp) {
    bf16 h0 = __float2bfloat16(v.x), h1 = __float2bfloat16(v.y);
    bf16 h2 = __float2bfloat16(v.z), h3 = __float2bfloat16(v.w);
    bf16 l0 = __float2bfloat16(v.x - __bfloat162float(h0));
    bf16 l1 = __float2bfloat16(v.y - __bfloat162float(h1));
    bf16 l2 = __float2bfloat16(v.z - __bfloat162float(h2));
    bf16 l3 = __float2bfloat16(v.w - __bfloat162float(h3));
    __nv_bfloat162 ha = __halves2bfloat162(h0, h1), hb = __halves2bfloat162(h2, h3);
    __nv_bfloat162 la = __halves2bfloat162(l0, l1), lb = __halves2bfloat162(l2, l3);
    uint2 hh, ll;
    hh.x = *reinterpret_cast<uint32_t*>(&ha);
    hh.y = *reinterpret_cast<uint32_t*>(&hb);
    ll.x = *reinterpret_cast<uint32_t*>(&la);
    ll.y = *reinterpret_cast<uint32_t*>(&lb);
    *hp = hh;
    *lp = ll;
}

__device__ __forceinline__ uint32_t smem_u32(const void* p) {
    uint32_t a;
    asm("{ .reg .u64 t; cvta.to.shared.u64 t, %1; cvt.u32.u64 %0, t; }"
        : "=r"(a) : "l"(p));
    return a;
}

__device__ __forceinline__ void cp16(uint32_t dst, const void* src) {
    asm volatile("cp.async.cg.shared.global [%0], [%1], 16;"
                 :: "r"(dst), "l"(src));
}
__device__ __forceinline__ void cp16z(uint32_t dst, const void* src, int sz) {
    asm volatile("cp.async.cg.shared.global [%0], [%1], 16, %2;"
                 :: "r"(dst), "l"(src), "r"(sz));
}
__device__ __forceinline__ void cp_commit() {
    asm volatile("cp.async.commit_group;" ::: "memory");
}

// Stage layout: A_h @0 (16KB), A_l @16384, B_h @32768 (NT*128B), B_l after.
template<int NT>
__device__ __forceinline__ void load_chunk_cp(
    uint32_t sb, const bf16* Ah, const bf16* Al,
    const bf16* Bh, const bf16* Bl,
    int bm, int bn, int N, int K, int k0, int tid)
{
    #pragma unroll
    for (int p = 0; p < 4; ++p) {
        int id = tid + p * 256;
        int row = id >> 3, grp = id & 7;
        uint32_t boff = (uint32_t)(row * 128 + grp * 16);
        uint32_t sw = boff ^ ((boff >> 3) & 0x70);
        size_t ao = (size_t)(bm + row) * K + k0 + grp * 8;
        cp16(sb + sw,         Ah + ao);
        cp16(sb + 16384 + sw, Al + ao);
    }
    const uint32_t bBh = sb + 32768;
    const uint32_t bBl = sb + 32768 + NT * 128;
    #pragma unroll
    for (int p = 0; p < NT / 32; ++p) {
        int id = tid + p * 256;
        int row = id >> 3, grp = id & 7;
        uint32_t boff = (uint32_t)(row * 128 + grp * 16);
        uint32_t sw = boff ^ ((boff >> 3) & 0x70);
        int brow = bn + row;
        int ok = (brow < N) ? 16 : 0;
        size_t bo = (size_t)(brow < N ? brow : 0) * K + k0 + grp * 8;
        cp16z(bBh + sw, Bh + bo, ok);
        cp16z(bBl + sw, Bl + bo, ok);
    }
    cp_commit();
}

#if HAS_TCGEN05
// ---------------------------------------------------------------------------
// tcgen05 PTX helpers (compiled ONLY on the sm_103a/sm_100a pass)
// ---------------------------------------------------------------------------
__device__ __forceinline__ uint32_t elect1() {
    uint32_t r;
    asm volatile("{\n\t.reg .pred p;\n\telect.sync _|p, 0xFFFFFFFF;\n\t"
                 "selp.b32 %0,1,0,p;\n\t}" : "=r"(r));
    return r;
}
__device__ __forceinline__ void tc_alloc(uint32_t saddr, uint32_t ncols) {
    asm volatile("tcgen05.alloc.cta_group::1.sync.aligned.shared::cta.b32 [%0], %1;"
                 :: "r"(saddr), "r"(ncols) : "memory");
}
__device__ __forceinline__ void tc_relinq() {
    asm volatile("tcgen05.relinquish_alloc_permit.cta_group::1.sync.aligned;");
}
__device__ __forceinline__ void tc_dealloc(uint32_t tmem, uint32_t ncols) {
    asm volatile("tcgen05.dealloc.cta_group::1.sync.aligned.b32 %0, %1;"
                 :: "r"(tmem), "r"(ncols));
}
__device__ __forceinline__ void mbar_init(uint32_t mb, uint32_t cnt) {
    asm volatile("mbarrier.init.shared.b64 [%0], %1;" :: "r"(mb), "r"(cnt) : "memory");
}
__device__ __forceinline__ void mbar_wait(uint32_t mb, uint32_t parity) {
    asm volatile("{\n\t.reg .pred P;\n\t"
                 "WL_%=:\n\t"
                 "mbarrier.try_wait.parity.acquire.cta.shared::cta.b64 P, [%0], %1, 0x989680;\n\t"
                 "@!P bra WL_%=;\n\t}"
                 :: "r"(mb), "r"(parity) : "memory");
}
__device__ __forceinline__ void tc_commit(uint32_t mb) {
    asm volatile("tcgen05.commit.cta_group::1.mbarrier::arrive::one.shared::cluster.b64 [%0];"
                 :: "r"(mb) : "memory");
}
__device__ __forceinline__ void fence_async_smem() {
    asm volatile("fence.proxy.async.shared::cta;" ::: "memory");
}
__device__ __forceinline__ void tc_fence_after() {
    asm volatile("tcgen05.fence::after_thread_sync;" ::: "memory");
}
__device__ __forceinline__ void tc_wait_ld() {
    asm volatile("tcgen05.wait::ld.sync.aligned;" ::: "memory");
}
__device__ __forceinline__ void mma_ss(uint32_t d, uint64_t a, uint64_t b,
                                       uint32_t idesc, bool en) {
    uint32_t e = en ? 1u : 0u;
    asm volatile("{\n\t.reg .pred p;\n\tsetp.ne.u32 p, %4, 0;\n\t"
                 "tcgen05.mma.cta_group::1.kind::f16 [%0], %1, %2, %3, "
                 "{%5, %5, %5, %5}, p;\n\t}"
                 :: "r"(d), "l"(a), "l"(b), "r"(idesc), "r"(e), "r"(0u)
                 : "memory");
}
__device__ __forceinline__ void ldtm32(uint32_t* r, uint32_t tmem) {
    asm volatile(
        "tcgen05.ld.sync.aligned.32x32b.x32.b32 "
        "{%0, %1, %2, %3, %4, %5, %6, %7, %8, %9, %10, %11, %12, %13, %14, %15, "
        "%16, %17, %18, %19, %20, %21, %22, %23, %24, %25, %26, %27, %28, %29, %30, %31}, [%32];"
        : "=r"(r[0]), "=r"(r[1]), "=r"(r[2]), "=r"(r[3]),
          "=r"(r[4]), "=r"(r[5]), "=r"(r[6]), "=r"(r[7]),
          "=r"(r[8]), "=r"(r[9]), "=r"(r[10]), "=r"(r[11]),
          "=r"(r[12]), "=r"(r[13]), "=r"(r[14]), "=r"(r[15]),
          "=r"(r[16]), "=r"(r[17]), "=r"(r[18]), "=r"(r[19]),
          "=r"(r[20]), "=r"(r[21]), "=r"(r[22]), "=r"(r[23]),
          "=r"(r[24]), "=r"(r[25]), "=r"(r[26]), "=r"(r[27]),
          "=r"(r[28]), "=r"(r[29]), "=r"(r[30]), "=r"(r[31])
        : "r"(tmem));
}
__device__ __forceinline__ uint64_t mk_desc(uint32_t saddr) {
    const uint64_t base = (uint64_t(2) << 61) | (uint64_t(1) << 46)
                        | (uint64_t(64) << 32) | (uint64_t(1) << 16);
    return base | ((uint64_t)(saddr >> 4) & 0x3FFF);
}
#define IDESC_128 ((1u << 4) | (1u << 7) | (1u << 10) | (16u << 17) | (8u << 24))
#endif // HAS_TCGEN05

// Fallback warp MMA (legal on any sm_80+ target)
__device__ __forceinline__ void mma16816(float* d, uint32_t a0, uint32_t a1,
                                         uint32_t a2, uint32_t a3,
                                         uint32_t b0, uint32_t b1) {
    asm volatile(
        "mma.sync.aligned.m16n8k16.row.col.f32.bf16.bf16.f32 "
        "{%0,%1,%2,%3}, {%4,%5,%6,%7}, {%8,%9}, {%0,%1,%2,%3};"
        : "+f"(d[0]), "+f"(d[1]), "+f"(d[2]), "+f"(d[3])
        : "r"(a0), "r"(a1), "r"(a2), "r"(a3), "r"(b0), "r"(b1));
}

// ---------------------------------------------------------------------------
// bf16-split GEMM: C[M,N] = act(A @ B^T + bias). Tile 128xNT (NT=128/256),
// K-chunk 64, 2-stage cp.async pipeline. NT=256 issued as 2x validated
// N=128 tcgen05 MMAs (d at tmem+0/+128, B-desc +1024).
// ---------------------------------------------------------------------------
#define STAGE_B(NT) (32768 + 2 * (NT) * 128)
#define SMEM_G(NT)  (1024 + 2 * STAGE_B(NT) + 1024)

template<int ACT, int OUTMODE, int NT>
__global__ __launch_bounds__(256)
void gemm_tc(const bf16* __restrict__ Ah, const bf16* __restrict__ Al,
             const bf16* __restrict__ Bh, const bf16* __restrict__ Bl,
             const float* __restrict__ bias,
             float* __restrict__ Cf, bf16* __restrict__ Ch, bf16* __restrict__ Cl,
             int M, int N, int K)
{
    extern __shared__ char dsm[];
    const uint32_t sraw = smem_u32(dsm);
    const uint32_t tile0 = (sraw + 1024u) & ~1023u;
    const uint32_t off0 = tile0 - sraw;
    const uint32_t STG = STAGE_B(NT);

    const int tid = threadIdx.x;
    const int wid = tid >> 5, lid = tid & 31;
    const int bm = blockIdx.y * 128;
    const int bn = blockIdx.x * NT;
    char* smc = dsm;
    const int nk = K >> 6;

#if HAS_TCGEN05
    const uint32_t mb0 = sraw + 8, mb1 = sraw + 16;

    if (wid == 0) { tc_alloc(sraw, (NT > 128) ? 256 : 128); tc_relinq(); }
    if (tid == 0) { mbar_init(mb0, 1); mbar_init(mb1, 1); }
    __syncthreads();
    uint32_t tmem;
    asm volatile("ld.shared.b32 %0, [%1];" : "=r"(tmem) : "r"(sraw));

    load_chunk_cp<NT>(tile0, Ah, Al, Bh, Bl, bm, bn, N, K, 0, tid);

    int ph0 = 0, ph1 = 0;
    for (int k = 0; k < nk; ++k) {
        const int s = k & 1;
        if (k + 1 < nk) {
            if (k >= 1) {
                if (((k + 1) & 1) == 0) { mbar_wait(mb0, ph0); ph0 ^= 1; }
                else                    { mbar_wait(mb1, ph1); ph1 ^= 1; }
            }
            load_chunk_cp<NT>(tile0 + ((k + 1) & 1) * STG,
                              Ah, Al, Bh, Bl, bm, bn, N, K, (k + 1) * 64, tid);
            asm volatile("cp.async.wait_group 1;" ::: "memory");
        } else {
            asm volatile("cp.async.wait_group 0;" ::: "memory");
        }
        fence_async_smem();
        __syncthreads();

        if (wid == 0) {
            if (elect1()) {
                uint32_t base = tile0 + s * STG;
                uint64_t dah = mk_desc(base);
                uint64_t dal = mk_desc(base + 16384);
                uint64_t dbh = mk_desc(base + 32768);
                uint64_t dbl = mk_desc(base + 32768 + NT * 128);
                #pragma unroll
                for (int ks = 0; ks < 4; ++ks) {
                    uint64_t o = (uint64_t)(ks * 2);
                    bool en0 = (k > 0) || (ks > 0);
                    mma_ss(tmem, dah + o, dbh + o, IDESC_128, en0);
                    mma_ss(tmem, dah + o, dbl + o, IDESC_128, true);
                    mma_ss(tmem, dal + o, dbh + o, IDESC_128, true);
                    if (NT > 128) {
                        mma_ss(tmem + 128, dah + o, dbh + 1024 + o, IDESC_128, en0);
                        mma_ss(tmem + 128, dah + o, dbl + 1024 + o, IDESC_128, true);
                        mma_ss(tmem + 128, dal + o, dbh + 1024 + o, IDESC_128, true);
                    }
                }
                tc_commit(s == 0 ? mb0 : mb1);
            }
        }
    }
    if (((nk - 1) & 1) == 0) mbar_wait(mb0, ph0);
    else                     mbar_wait(mb1, ph1);
    tc_fence_after();
    __syncthreads();

    // Coalesced epilogue: LDTM -> smem (pad 33) -> lane=col global stores
    float* sf = (float*)(smc + off0);
    #pragma unroll
    for (int nb = 0; nb < NT / 32; ++nb) {
        if (wid < 4) {
            uint32_t dr[32];
            ldtm32(dr, tmem + nb * 32);
            tc_wait_ld();
            int mrow = wid * 32 + lid;
            #pragma unroll
            for (int c = 0; c < 32; ++c) sf[mrow * 33 + c] = __uint_as_float(dr[c]);
        }
        __syncthreads();
        int cb = bn + nb * 32;
        if (cb < N) {
            int col = cb + lid;
            bool okc = (col < N);
            float bv = (bias && okc) ? bias[col] : 0.0f;
            int rbase = (tid >> 5) * 16;
            if (okc) {
                #pragma unroll
                for (int rr = 0; rr < 16; ++rr) {
                    int row = rbase + rr;
                    float v = sf[row * 33 + lid] + bv;
                    if (ACT) v = fmaxf(v, 0.0f);
                    size_t idx = (size_t)(bm + row) * N + col;
                    if (OUTMODE == 0) {
                        Cf[idx] = v;
                    } else {
                        bf16 h = __float2bfloat16(v);
                        Ch[idx] = h;
                        Cl[idx] = __float2bfloat16(v - __bfloat162float(h));
                    }
                }
            }
        }
        __syncthreads();
    }
    if (wid == 0) tc_dealloc(tmem, (NT > 128) ? 256 : 128);

#else  // ------------------- mma.sync fallback path -------------------------
    const int NTW = NT / 4;            // warp n-extent
    const int NNT = NT / 32;           // n-tiles per warp
    const int wm0 = (wid >> 2) * 64;
    const int wn0 = (wid & 3) * NTW;
    const int g = lid >> 2, tg = lid & 3;

    float acc[4][NT / 32][4];
    #pragma unroll
    for (int a = 0; a < 4; ++a)
        #pragma unroll
        for (int b = 0; b < NNT; ++b)
            #pragma unroll
            for (int c = 0; c < 4; ++c) acc[a][b][c] = 0.0f;

    load_chunk_cp<NT>(tile0, Ah, Al, Bh, Bl, bm, bn, N, K, 0, tid);

    for (int k = 0; k < nk; ++k) {
        const uint32_t oS = off0 + (uint32_t)(k & 1) * STG;
        if (k + 1 < nk) {
            load_chunk_cp<NT>(tile0 + ((k + 1) & 1) * STG,
                              Ah, Al, Bh, Bl, bm, bn, N, K, (k + 1) * 64, tid);
            asm volatile("cp.async.wait_group 1;" ::: "memory");
        } else {
            asm volatile("cp.async.wait_group 0;" ::: "memory");
        }
        __syncthreads();

        const uint32_t oA_h = oS, oA_l = oS + 16384;
        const uint32_t oB_h = oS + 32768, oB_l = oS + 32768 + NT * 128;

        #pragma unroll
        for (int ks = 0; ks < 4; ++ks) {
            const uint32_t kb = (uint32_t)(ks * 32 + tg * 4);
            uint32_t bh0[NT / 32], bh1[NT / 32], bl0[NT / 32], bl1[NT / 32];
            #pragma unroll
            for (int nt = 0; nt < NNT; ++nt) {
                uint32_t row = (uint32_t)(wn0 + nt * 8 + g);
                uint32_t o1 = row * 128 + kb;
                uint32_t o2 = o1 + 16;
                uint32_t s1 = o1 ^ ((o1 >> 3) & 0x70);
                uint32_t s2 = o2 ^ ((o2 >> 3) & 0x70);
                bh0[nt] = *(const uint32_t*)(smc + oB_h + s1);
                bh1[nt] = *(const uint32_t*)(smc + oB_h + s2);
                bl0[nt] = *(const uint32_t*)(smc + oB_l + s1);
                bl1[nt] = *(const uint32_t*)(smc + oB_l + s2);
            }
            #pragma unroll
            for (int mt = 0; mt < 4; ++mt) {
                uint32_t r0 = (uint32_t)(wm0 + mt * 16 + g);
                uint32_t o_r0c0 = r0 * 128 + kb;
                uint32_t o_r8c0 = o_r0c0 + 8 * 128;
                uint32_t o_r0c8 = o_r0c0 + 16;
                uint32_t o_r8c8 = o_r8c0 + 16;
                uint32_t s00 = o_r0c0 ^ ((o_r0c0 >> 3) & 0x70);
                uint32_t s80 = o_r8c0 ^ ((o_r8c0 >> 3) & 0x70);
                uint32_t s08 = o_r0c8 ^ ((o_r0c8 >> 3) & 0x70);
                uint32_t s88 = o_r8c8 ^ ((o_r8c8 >> 3) & 0x70);
                uint32_t ah0 = *(const uint32_t*)(smc + oA_h + s00);
                uint32_t ah1 = *(const uint32_t*)(smc + oA_h + s80);
                uint32_t ah2 = *(const uint32_t*)(smc + oA_h + s08);
                uint32_t ah3 = *(const uint32_t*)(smc + oA_h + s88);
                uint32_t al0 = *(const uint32_t*)(smc + oA_l + s00);
                uint32_t al1 = *(const uint32_t*)(smc + oA_l + s80);
                uint32_t al2 = *(const uint32_t*)(smc + oA_l + s08);
                uint32_t al3 = *(const uint32_t*)(smc + oA_l + s88);
                #pragma unroll
                for (int nt = 0; nt < NNT; ++nt) {
                    mma16816(acc[mt][nt], ah0, ah1, ah2, ah3, bh0[nt], bh1[nt]);
                    mma16816(acc[mt][nt], ah0, ah1, ah2, ah3, bl0[nt], bl1[nt]);
                    mma16816(acc[mt][nt], al0, al1, al2, al3, bh0[nt], bh1[nt]);
                }
            }
        }
        __syncthreads();
    }

    #pragma unroll
    for (int mt = 0; mt < 4; ++mt) {
        #pragma unroll
        for (int nt = 0; nt < NNT; ++nt) {
            int r0 = bm + wm0 + mt * 16 + g;
            int c0 = bn + wn0 + nt * 8 + tg * 2;
            #pragma unroll
            for (int half = 0; half < 2; ++half) {
                int row = r0 + half * 8;
                #pragma unroll
                for (int cc = 0; cc < 2; ++cc) {
                    int col = c0 + cc;
                    if (col < N) {
                        float v = acc[mt][nt][half * 2 + cc];
                        if (bias) v += bias[col];
                        if (ACT) v = fmaxf(v, 0.0f);
                        size_t idx = (size_t)row * N + col;
                        if (OUTMODE == 0) {
                            Cf[idx] = v;
                        } else {
                            bf16 h = __float2bfloat16(v);
                            Ch[idx] = h;
                            Cl[idx] = __float2bfloat16(v - __bfloat162float(h));
                        }
                    }
                }
            }
        }
    }
#endif
}

// ---------------------------------------------------------------------------
// Split fp32 -> bf16 hi/lo (vectorized)
// ---------------------------------------------------------------------------
__global__ __launch_bounds__(256)
void split_kernel(const float4* __restrict__ x, uint2* __restrict__ h,
                  uint2* __restrict__ l, int n4)
{
    int i = blockIdx.x * 256 + threadIdx.x;
    if (i < n4) pack4(x[i], h + i, l + i);
}

// ---------------------------------------------------------------------------
// LayerNorm: one block per row of 512, emits bf16 hi/lo
// ---------------------------------------------------------------------------
__global__ __launch_bounds__(256)
void ln_kernel(const float* __restrict__ x, const float* __restrict__ g,
               const float* __restrict__ b, bf16* __restrict__ yh,
               bf16* __restrict__ yl)
{
    __shared__ float rbuf[8];
    __shared__ float smean, srstd;
    const int row = blockIdx.x;
    const int tid = threadIdx.x;
    const int lane = tid & 31, warp = tid >> 5;
    const float* xr = x + (size_t)row * D_MODEL;

    float v0 = xr[tid], v1 = xr[tid + 256];

    float s = v0 + v1;
    #pragma unroll
    for (int o = 16; o; o >>= 1) s += __shfl_down_sync(0xffffffffu, s, o);
    if (!lane) rbuf[warp] = s;
    __syncthreads();
    if (warp == 0) {
        float t = (lane < 8) ? rbuf[lane] : 0.0f;
        #pragma unroll
        for (int o = 4; o; o >>= 1) t += __shfl_down_sync(0xffffffffu, t, o);
        if (!lane) smean = t * (1.0f / D_MODEL);
    }
    __syncthreads();
    float m = smean;

    float d0 = v0 - m, d1 = v1 - m;
    float sv = d0 * d0 + d1 * d1;
    #pragma unroll
    for (int o = 16; o; o >>= 1) sv += __shfl_down_sync(0xffffffffu, sv, o);
    if (!lane) rbuf[warp] = sv;
    __syncthreads();
    if (warp == 0) {
        float t = (lane < 8) ? rbuf[lane] : 0.0f;
        #pragma unroll
        for (int o = 4; o; o >>= 1) t += __shfl_down_sync(0xffffffffu, t, o);
        if (!lane) srstd = rsqrtf(t * (1.0f / D_MODEL) + 1e-5f);
    }
    __syncthreads();
    float r = srstd;

    size_t base = (size_t)row * D_MODEL;
    float o0 = d0 * r * g[tid]       + b[tid];
    float o1 = d1 * r * g[tid + 256] + b[tid + 256];
    split1(o0, yh + base + tid,       yl + base + tid);
    split1(o1, yh + base + tid + 256, yl + base + tid + 256);
}

// ---------------------------------------------------------------------------
// Fused scan + attention-core kernel (emits attncore bf16 hi/lo)
// ---------------------------------------------------------------------------
__global__ __launch_bounds__(256)
void scan_kernel(const float* __restrict__ allproj, const int* __restrict__ terms,
                 const float* __restrict__ tick, const float* __restrict__ tk,
                 const float* __restrict__ tv, const float* __restrict__ s_prev,
                 bf16* __restrict__ core_h, bf16* __restrict__ core_l)
{
    const int bh = blockIdx.x;
    const int b = bh >> 3, h = bh & 7;
    const int tid = threadIdx.x;
    const int lane = tid & 31, warp = tid >> 5;

    __shared__ float sk[64], sq[64], sv[64], sb[64], sg[64];
    __shared__ float sp[12], socc[8];
    __shared__ float red[9 * 8];
    __shared__ float kdqn[9];
    __shared__ float kvpart[256];
    __shared__ float sterm;

    const int d  = tid >> 2, j = tid & 3;
    const int d2 = tid & 63, r0 = tid >> 6;

    float Kst[8], S, V0, V1;
    #pragma unroll
    for (int r = 0; r < 8; ++r)
        Kst[r] = tk[(((size_t)b * R_ + r) * H_ + h) * 256 + tid];
    S  = s_prev[((size_t)b * H_ + h) * 256 + tid];
    V0 = tv[(((size_t)b * R_ + r0    ) * H_ + h) * 64 + d2];
    V1 = tv[(((size_t)b * R_ + r0 + 4) * H_ + h) * 64 + d2];
    const float tickb = tick[b];

    for (int t = 0; t < T_; ++t) {
        const size_t rowbase = ((size_t)t * B_ + b) * TOTAL_PROJ;
        const float* ap = allproj + rowbase + h * 320;
        if (tid < 64) {
            sk[tid] = ap[tid];
            sq[tid] = ap[64 + tid];
            sv[tid] = ap[128 + tid];
            sb[tid] = ap[192 + tid];
            sg[tid] = ap[256 + tid];
        } else if (tid < 76) {
            sp[tid - 64] = allproj[rowbase + KQV_DIM + h * 12 + (tid - 64)];
        } else if (tid >= 96 && tid < 104) {
            int u = tid - 96;
            float om = -3.14159265358979323846f
                     + (float)u * (6.28318530717958647692f / 7.0f);
            socc[u] = cosf((tickb + (float)(t + 1)) * om);
        } else if (tid == 255) {
            sterm = 1.0f - (float)terms[t * B_ + b];
        }
        __syncthreads();

        const float term = sterm;

        float ke = fmaxf(sk[d], 0.0f) * fmaxf(sp[j], 0.0f);
        float qe = fmaxf(sq[d], 0.0f) * fmaxf(sp[4 + j], 0.0f);
        float ge = sigf(sg[d]) * sigf(sp[8 + j]);
        float kg = ke * ge;
        float dg = (1.0f - ge) * term;
        S = fmaf(dg, S, kg);
        float loc[9];
        #pragma unroll
        for (int r = 0; r < 8; ++r) {
            Kst[r] = fmaf(dg, Kst[r], kg * socc[r]);
            loc[r] = Kst[r] * qe;
        }
        loc[8] = S * qe;

        float bs = sigf(sb[d2]);
        float vg = sv[d2] * bs;
        float db = (1.0f - bs) * term;
        V0 = fmaf(db, V0, vg * socc[r0]);
        V1 = fmaf(db, V1, vg * socc[r0 + 4]);

        #pragma unroll
        for (int v = 0; v < 9; ++v) {
            float x = loc[v];
            x += __shfl_down_sync(0xffffffffu, x, 16);
            x += __shfl_down_sync(0xffffffffu, x, 8);
            x += __shfl_down_sync(0xffffffffu, x, 4);
            x += __shfl_down_sync(0xffffffffu, x, 2);
            x += __shfl_down_sync(0xffffffffu, x, 1);
            if (lane == 0) red[v * 8 + warp] = x;
        }
        __syncthreads();
        if (tid < 9) {
            float s = 0.0f;
            #pragma unroll
            for (int w = 0; w < 8; ++w) s += red[tid * 8 + w];
            kdqn[tid] = (tid == 8) ? (s + 1e-6f) : s;
        }
        __syncthreads();

        kvpart[tid] = V0 * kdqn[r0] + V1 * kdqn[r0 + 4];
        __syncthreads();
        if (tid < 64) {
            float kv = kvpart[tid] + kvpart[64 + tid]
                     + kvpart[128 + tid] + kvpart[192 + tid];
            float val = kv / (16.0f * kdqn[8]);
            size_t idx = ((size_t)t * B_ + b) * D_MODEL + h * 64 + tid;
            split1(val, core_h + idx, core_l + idx);
        }
        __syncthreads();
    }
}

// ---------------------------------------------------------------------------
// GRU stage 1 (vectorized)
// ---------------------------------------------------------------------------
__global__ __launch_bounds__(256)
void gru_pre(const float4* __restrict__ x, const float* __restrict__ Y3,
             const float* __restrict__ X2, uint2* __restrict__ rxh,
             uint2* __restrict__ rxl, float4* __restrict__ z, int n4)
{
    int i = blockIdx.x * 256 + threadIdx.x;
    if (i >= n4) return;
    int row = i >> 7, c = (i & 127) * 4;
    const float4 y0 = *(const float4*)&Y3[(size_t)row * 1536 + c];
    const float4 y1 = *(const float4*)&Y3[(size_t)row * 1536 + 512 + c];
    const float4 x0 = *(const float4*)&X2[(size_t)row * 1024 + c];
    const float4 x1 = *(const float4*)&X2[(size_t)row * 1024 + 512 + c];
    float4 xv = x[i];
    float4 zz;
    zz.x = sigf(y1.x + x1.x - 2.0f);
    zz.y = sigf(y1.y + x1.y - 2.0f);
    zz.z = sigf(y1.z + x1.z - 2.0f);
    zz.w = sigf(y1.w + x1.w - 2.0f);
    float4 rx;
    rx.x = sigf(y0.x + x0.x) * xv.x;
    rx.y = sigf(y0.y + x0.y) * xv.y;
    rx.z = sigf(y0.z + x0.z) * xv.z;
    rx.w = sigf(y0.w + x0.w) * xv.w;
    z[i] = zz;
    pack4(rx, rxh + i, rxl + i);
}

// ---------------------------------------------------------------------------
// GRU stage 2 (vectorized)
// ---------------------------------------------------------------------------
__global__ __launch_bounds__(256)
void gru_post(const float4* __restrict__ x, const float* __restrict__ Y3,
              const float4* __restrict__ RX, const float4* __restrict__ z,
              float4* __restrict__ out, uint2* __restrict__ oh,
              uint2* __restrict__ ol, int n4)
{
    int i = blockIdx.x * 256 + threadIdx.x;
    if (i >= n4) return;
    int row = i >> 7, c = (i & 127) * 4;
    const float4 y2 = *(const float4*)&Y3[(size_t)row * 1536 + 1024 + c];
    float4 rxv = RX[i], zz = z[i], xv = x[i];
    float4 v;
    v.x = (1.0f - zz.x) * xv.x + zz.x * tanhf(y2.x + rxv.x);
    v.y = (1.0f - zz.y) * xv.y + zz.y * tanhf(y2.y + rxv.y);
    v.z = (1.0f - zz.z) * xv.z + zz.z * tanhf(y2.z + rxv.z);
    v.w = (1.0f - zz.w) * xv.w + zz.w * tanhf(y2.w + rxv.w);
    out[i] = v;
    if (oh) pack4(v, oh + i, ol + i);
}

// ---------------------------------------------------------------------------
// Launch
// ---------------------------------------------------------------------------
template<typename Tp>
static Tp* symptr(const void* sym) {
    void* p = nullptr;
    cudaGetSymbolAddress(&p, sym);
    return (Tp*)p;
}

extern "C" void kernel_launch(void* const* d_in, const int* in_sizes, int n_in,
                              void* d_out, int out_size)
{
    const float* inputs   = (const float*)d_in[0];
    const int*   terms    = (const int*)  d_in[1];
    const float* tilde_k  = (const float*)d_in[2];
    const float* tilde_v  = (const float*)d_in[3];
    const float* s_prev   = (const float*)d_in[4];
    const float* tick     = (const float*)d_in[5];
    const float* w_proj   = (const float*)d_in[6];
    const float* b_proj   = (const float*)d_in[7];
    const float* w_attn   = (const float*)d_in[8];
    const float* b_attn   = (const float*)d_in[9];
    const float* ln1_g    = (const float*)d_in[10];
    const float* ln1_b    = (const float*)d_in[11];
    const float* ln2_g    = (const float*)d_in[12];
    const float* ln2_b    = (const float*)d_in[13];
    const float* gru1_w   = (const float*)d_in[14];
    const float* gru1_u   = (const float*)d_in[15];
    const float* gru2_w   = (const float*)d_in[16];
    const float* gru2_u   = (const float*)d_in[17];
    const float* ffc_w1   = (const float*)d_in[18];
    const float* ffc_b1   = (const float*)d_in[19];
    const float* ffc_w2   = (const float*)d_in[20];
    const float* ffc_b2   = (const float*)d_in[21];
    float* out = (float*)d_out;

    float* allproj = symptr<float>(g_allproj);
    float* Y3   = symptr<float>(g_Y3);
    float* X2   = symptr<float>(g_X2);
    float* zb   = symptr<float>(g_zb);
    float* RX   = symptr<float>(g_RX);
    float* gate1= symptr<float>(g_gate1);

    bf16 *in_h = symptr<bf16>(g_in_h),  *in_l = symptr<bf16>(g_in_l);
    bf16 *xn_h = symptr<bf16>(g_xn_h),  *xn_l = symptr<bf16>(g_xn_l);
    bf16 *co_h = symptr<bf16>(g_core_h),*co_l = symptr<bf16>(g_core_l);
    bf16 *ar_h = symptr<bf16>(g_arelu_h),*ar_l= symptr<bf16>(g_arelu_l);
    bf16 *rx_h = symptr<bf16>(g_rx_h),  *rx_l = symptr<bf16>(g_rx_l);
    bf16 *g1_h = symptr<bf16>(g_g1_h),  *g1_l = symptr<bf16>(g_g1_l);
    bf16 *ff_h = symptr<bf16>(g_ff_h),  *ff_l = symptr<bf16>(g_ff_l);
    bf16 *hd_h = symptr<bf16>(g_hid_h), *hd_l = symptr<bf16>(g_hid_l);

    bf16 *wp_h = symptr<bf16>(g_wproj_h), *wp_l = symptr<bf16>(g_wproj_l);
    bf16 *wa_h = symptr<bf16>(g_wattn_h), *wa_l = symptr<bf16>(g_wattn_l);
    bf16 *w1w_h= symptr<bf16>(g_g1w_h),   *w1w_l= symptr<bf16>(g_g1w_l);
    bf16 *w1u_h= symptr<bf16>(g_g1u_h),   *w1u_l= symptr<bf16>(g_g1u_l);
    bf16 *w2w_h= symptr<bf16>(g_g2w_h),   *w2w_l= symptr<bf16>(g_g2w_l);
    bf16 *w2u_h= symptr<bf16>(g_g2u_h),   *w2u_l= symptr<bf16>(g_g2u_l);
    bf16 *f1_h = symptr<bf16>(g_fw1_h),   *f1_l = symptr<bf16>(g_fw1_l);
    bf16 *f2_h = symptr<bf16>(g_fw2_h),   *f2_l = symptr<bf16>(g_fw2_l);

    cudaFuncSetAttribute(gemm_tc<0,0,128>, cudaFuncAttributeMaxDynamicSharedMemorySize, SMEM_G(128));
    cudaFuncSetAttribute(gemm_tc<1,1,128>, cudaFuncAttributeMaxDynamicSharedMemorySize, SMEM_G(128));
    cudaFuncSetAttribute(gemm_tc<0,0,256>, cudaFuncAttributeMaxDynamicSharedMemorySize, SMEM_G(256));
    cudaFuncSetAttribute(gemm_tc<1,1,256>, cudaFuncAttributeMaxDynamicSharedMemorySize, SMEM_G(256));

    const int n = NTOK * D_MODEL;
    const int n4 = n / 4;
    dim3 thr(256);
    const int eg4 = (n4 + 255) / 256;
    const int OFF2 = 2 * D_MODEL * D_MODEL;

    #define SPLIT(src, dh, dl, cnt) \
        split_kernel<<<((cnt)/4 + 255) / 256, thr>>>( \
            (const float4*)(src), (uint2*)(dh), (uint2*)(dl), (cnt)/4)

    SPLIT(inputs, in_h, in_l, n);
    ln_kernel<<<NTOK, thr>>>(inputs, ln1_g, ln1_b, xn_h, xn_l);
    SPLIT(w_proj, wp_h, wp_l, WPROJ_N);
    SPLIT(gru1_w, w1w_h, w1w_l, WGRU_N);
    SPLIT(gru1_u, w1u_h, w1u_l, WGRU_N);

    // all_proj (4096 x 2656 x 512), NT=256
    gemm_tc<0,0,256><<<dim3((TOTAL_PROJ + 255) / 256, 32), thr, SMEM_G(256)>>>(
        xn_h, xn_l, wp_h, wp_l, b_proj, allproj, nullptr, nullptr,
        NTOK, TOTAL_PROJ, D_MODEL);

    SPLIT(w_attn, wa_h, wa_l, WATTN_N);
    SPLIT(gru2_w, w2w_h, w2w_l, WGRU_N);
    SPLIT(gru2_u, w2u_h, w2u_l, WGRU_N);
    SPLIT(ffc_w1, f1_h, f1_l, WFFC1_N);
    SPLIT(ffc_w2, f2_h, f2_l, WFFC2_N);

    // scan -> attncore hi/lo
    scan_kernel<<<B_ * H_, thr>>>(allproj, terms, tick, tilde_k, tilde_v,
                                  s_prev, co_h, co_l);

    // attnrelu = relu(core @ w_attn^T + b_attn), NT=128
    gemm_tc<1,1,128><<<dim3(4, 32), thr, SMEM_G(128)>>>(
        co_h, co_l, wa_h, wa_l, b_attn, nullptr, ar_h, ar_l,
        NTOK, D_MODEL, D_MODEL);

    // GRU1
    gemm_tc<0,0,256><<<dim3(6, 32), thr, SMEM_G(256)>>>(
        ar_h, ar_l, w1w_h, w1w_l, nullptr, Y3, nullptr, nullptr,
        NTOK, 3 * D_MODEL, D_MODEL);
    gemm_tc<0,0,256><<<dim3(4, 32), thr, SMEM_G(256)>>>(
        in_h, in_l, w1u_h, w1u_l, nullptr, X2, nullptr, nullptr,
        NTOK, 2 * D_MODEL, D_MODEL);
    gru_pre<<<eg4, thr>>>((const float4*)inputs, Y3, X2,
                          (uint2*)rx_h, (uint2*)rx_l, (float4*)zb, n4);
    gemm_tc<0,0,128><<<dim3(4, 32), thr, SMEM_G(128)>>>(
        rx_h, rx_l, w1u_h + OFF2, w1u_l + OFF2, nullptr, RX, nullptr, nullptr,
        NTOK, D_MODEL, D_MODEL);
    gru_post<<<eg4, thr>>>((const float4*)inputs, Y3, (const float4*)RX,
                           (const float4*)zb, (float4*)gate1,
                           (uint2*)g1_h, (uint2*)g1_l, n4);

    // ln2
    ln_kernel<<<NTOK, thr>>>(gate1, ln2_g, ln2_b, xn_h, xn_l);

    // FFC
    gemm_tc<1,1,256><<<dim3(8, 32), thr, SMEM_G(256)>>>(
        xn_h, xn_l, f1_h, f1_l, ffc_b1, nullptr, hd_h, hd_l,
        NTOK, D_FFC, D_MODEL);
    gemm_tc<1,1,128><<<dim3(4, 32), thr, SMEM_G(128)>>>(
        hd_h, hd_l, f2_h, f2_l, ffc_b2, nullptr, ff_h, ff_l,
        NTOK, D_MODEL, D_FFC);

    // GRU2 -> out
    gemm_tc<0,0,256><<<dim3(6, 32), thr, SMEM_G(256)>>>(
        ff_h, ff_l, w2w_h, w2w_l, nullptr, Y3, nullptr, nullptr,
        NTOK, 3 * D_MODEL, D_MODEL);
    gemm_tc<0,0,256><<<dim3(4, 32), thr, SMEM_G(256)>>>(
        g1_h, g1_l, w2u_h, w2u_l, nullptr, X2, nullptr, nullptr,
        NTOK, 2 * D_MODEL, D_MODEL);
    gru_pre<<<eg4, thr>>>((const float4*)gate1, Y3, X2,
                          (uint2*)rx_h, (uint2*)rx_l, (float4*)zb, n4);
    gemm_tc<0,0,128><<<dim3(4, 32), thr, SMEM_G(128)>>>(
        rx_h, rx_l, w2u_h + OFF2, w2u_l + OFF2, nullptr, RX, nullptr, nullptr,
        NTOK, D_MODEL, D_MODEL);
    gru_post<<<eg4, thr>>>((const float4*)gate1, Y3, (const float4*)RX,
                           (const float4*)zb, (float4*)out,
                           nullptr, nullptr, n4);
    #undef SPLIT
}